// round 11
// baseline (speedup 1.0000x reference)
#include <cuda_runtime.h>
#include <math.h>
#include <stdint.h>

#define N_NODES 30000
#define N_EDGES 480000
#define FIN 25
#define FE   14
#define DD   256
#define NG   512

// edge kernel dynamic smem: Xs 16*64 + Ws 16*256 + Ts 64*260 floats + 128 ints
#define EDGE_SMEM ((16 * 64 + 16 * 256 + 64 * 260 + 128) * 4)

// ---------------- device scratch (no allocations allowed) ----------------
__device__ __align__(16) float g_h0[N_NODES * DD];
__device__ __align__(16) float g_agg[N_NODES * DD];
__device__ __align__(16) float g_out[N_NODES * DD];
__device__ __align__(16) float g_e[N_NODES];
__device__ __align__(16) float g_gates[NG * 4 * DD];
__device__ __align__(16) float g_h[NG * DD];
__device__ __align__(16) float g_c[NG * DD];
__device__ __align__(16) float g_qstar[NG * 2 * DD];
__device__ int g_start[NG + 1];

// ---------------- f32x2 helpers ----------------
__device__ __forceinline__ unsigned long long dup2(float v) {
    unsigned long long r;
    asm("mov.b64 %0, {%1, %1};" : "=l"(r) : "f"(v));
    return r;
}
__device__ __forceinline__ void ffma2(unsigned long long& d,
                                      unsigned long long a,
                                      unsigned long long b) {
    asm("fma.rn.f32x2 %0, %1, %2, %0;" : "+l"(d) : "l"(a), "l"(b));
}
__device__ __forceinline__ float2 up2(unsigned long long v) {
    float2 r;
    asm("mov.b64 {%0, %1}, %2;" : "=f"(r.x), "=f"(r.y) : "l"(v));
    return r;
}
__device__ __forceinline__ void red4(float* p, float4 v) {
    asm volatile("red.global.add.v4.f32 [%0], {%1, %2, %3, %4};"
                 :: "l"(p), "f"(v.x), "f"(v.y), "f"(v.z), "f"(v.w) : "memory");
}
__device__ __forceinline__ float sigm(float x) { return 1.f / (1.f + expf(-x)); }

// ---------------- kernels ----------------

__global__ void k_zero() {
    const int i = blockIdx.x * blockDim.x + threadIdx.x;
    const int stride = gridDim.x * blockDim.x;
    const float4 z = make_float4(0.f, 0.f, 0.f, 0.f);
    float4* agg4 = reinterpret_cast<float4*>(g_agg);
    for (int j = i; j < N_NODES * DD / 4; j += stride) agg4[j] = z;
    float4* h4 = reinterpret_cast<float4*>(g_h);
    float4* c4 = reinterpret_cast<float4*>(g_c);
    for (int j = i; j < NG * DD / 4; j += stride) { h4[j] = z; c4[j] = z; }
    float4* q4 = reinterpret_cast<float4*>(g_qstar);
    for (int j = i; j < NG * 2 * DD / 4; j += stride) q4[j] = z;
}

__global__ void k_offsets(const int* __restrict__ batch) {
    const int n = blockIdx.x * blockDim.x + threadIdx.x;
    if (n >= N_NODES) return;
    const int cur = batch[n];
    const int prev = (n == 0) ? -1 : batch[n - 1];
    for (int b = prev + 1; b <= cur; b++) g_start[b] = n;
    if (n == N_NODES - 1)
        for (int b = cur + 1; b <= NG; b++) g_start[b] = N_NODES;
}

// h0 = relu(x @ W0 + b0), K = 25
__global__ void k_lin0(const float* __restrict__ x, const float* __restrict__ W0,
                       const float* __restrict__ b0v) {
    __shared__ float Ws[FIN * DD];
    __shared__ float xs[16][FIN + 1];
    const int tid = threadIdx.x;
    for (int i = tid; i < FIN * DD; i += 256) Ws[i] = W0[i];
    const int n0 = blockIdx.x * 16;
    for (int i = tid; i < 16 * FIN; i += 256) {
        const int r = i / FIN, c = i % FIN;
        const int n = n0 + r;
        xs[r][c] = (n < N_NODES) ? x[n * FIN + c] : 0.f;
    }
    __syncthreads();
    const float bb = b0v[tid];
#pragma unroll 4
    for (int r = 0; r < 16; r++) {
        const int n = n0 + r;
        if (n >= N_NODES) break;
        float acc = bb;
#pragma unroll
        for (int k = 0; k < FIN; k++) acc = fmaf(xs[r][k], Ws[k * DD + tid], acc);
        g_h0[n * DD + tid] = fmaxf(acc, 0.f);
    }
}

// Fused edge MLP: t = relu([h0[src]||e] @ Wm1 + bm1); m = t @ Wm2 + bm2; agg[dst] += m
__global__ void __launch_bounds__(256) k_edge(
    const float* __restrict__ eattr,
    const float* __restrict__ Wm1, const float* __restrict__ bm1,
    const float* __restrict__ Wm2, const float* __restrict__ bm2,
    const int* __restrict__ ei) {
    extern __shared__ float sm[];
    float* Xs = sm;                       // [16][64] K-major
    float* Ws = sm + 16 * 64;             // [16][256]
    float* Ts = Ws + 16 * 256;            // [64][260]
    int* src_s = reinterpret_cast<int*>(Ts + 64 * 260);
    int* dst_s = src_s + 64;

    const int tid = threadIdx.x;
    const int tx = tid & 31;
    const int ty = tid >> 5;
    const int e0 = blockIdx.x * 64;
    const int cA = tx * 4;
    const int cB = 128 + tx * 4;

    if (tid < 64) src_s[tid] = ei[e0 + tid];
    else if (tid < 128) dst_s[tid - 64] = ei[N_EDGES + e0 + tid - 64];
    __syncthreads();

    unsigned long long acc[8][4];
#pragma unroll
    for (int r = 0; r < 8; r++)
#pragma unroll
        for (int p = 0; p < 4; p++) acc[r][p] = 0ULL;

    // ---- GEMM1: K = 272 (270 real, zero-padded) ----
    for (int k0 = 0; k0 < 272; k0 += 16) {
#pragma unroll
        for (int i = 0; i < 4; i++) {
            const int lin = i * 256 + tid;
            const int kg = k0 + (lin >> 6);
            float4 v = make_float4(0.f, 0.f, 0.f, 0.f);
            if (kg < 270) v = reinterpret_cast<const float4*>(Wm1 + kg * DD)[lin & 63];
            reinterpret_cast<float4*>(Ws)[lin] = v;
        }
#pragma unroll
        for (int i = 0; i < 4; i++) {
            const int lin = i * 256 + tid;
            const int kk = lin >> 6, e = lin & 63;
            const int kg = k0 + kk;
            float v = 0.f;
            if (kg < DD)       v = g_h0[src_s[e] * DD + kg];
            else if (kg < 270) v = eattr[(e0 + e) * FE + (kg - DD)];
            Xs[kk * 64 + e] = v;
        }
        __syncthreads();
#pragma unroll
        for (int kk = 0; kk < 16; kk++) {
            const float4 a0 = *reinterpret_cast<const float4*>(Xs + kk * 64 + ty * 8);
            const float4 a1 = *reinterpret_cast<const float4*>(Xs + kk * 64 + ty * 8 + 4);
            const ulonglong2 q0 = *reinterpret_cast<const ulonglong2*>(Ws + kk * 256 + cA);
            const ulonglong2 q1 = *reinterpret_cast<const ulonglong2*>(Ws + kk * 256 + cB);
            const float av[8] = {a0.x, a0.y, a0.z, a0.w, a1.x, a1.y, a1.z, a1.w};
#pragma unroll
            for (int r = 0; r < 8; r++) {
                const unsigned long long ad = dup2(av[r]);
                ffma2(acc[r][0], ad, q0.x);
                ffma2(acc[r][1], ad, q0.y);
                ffma2(acc[r][2], ad, q1.x);
                ffma2(acc[r][3], ad, q1.y);
            }
        }
        __syncthreads();
    }

    // ---- epilogue 1: + bm1, relu, stage to Ts ----
    {
        const float4 bA = *reinterpret_cast<const float4*>(bm1 + cA);
        const float4 bB = *reinterpret_cast<const float4*>(bm1 + cB);
#pragma unroll
        for (int r = 0; r < 8; r++) {
            const float2 v0 = up2(acc[r][0]), v1 = up2(acc[r][1]);
            const float2 v2 = up2(acc[r][2]), v3 = up2(acc[r][3]);
            const float4 oA = make_float4(fmaxf(v0.x + bA.x, 0.f), fmaxf(v0.y + bA.y, 0.f),
                                          fmaxf(v1.x + bA.z, 0.f), fmaxf(v1.y + bA.w, 0.f));
            const float4 oB = make_float4(fmaxf(v2.x + bB.x, 0.f), fmaxf(v2.y + bB.y, 0.f),
                                          fmaxf(v3.x + bB.z, 0.f), fmaxf(v3.y + bB.w, 0.f));
            const int row = ty * 8 + r;
            *reinterpret_cast<float4*>(&Ts[row * 260 + cA]) = oA;
            *reinterpret_cast<float4*>(&Ts[row * 260 + cB]) = oB;
            acc[r][0] = acc[r][1] = acc[r][2] = acc[r][3] = 0ULL;
        }
    }
    __syncthreads();

    // ---- GEMM2: K = 256 ----
    for (int k0 = 0; k0 < DD; k0 += 16) {
#pragma unroll
        for (int i = 0; i < 4; i++) {
            const int lin = i * 256 + tid;
            reinterpret_cast<float4*>(Ws)[lin] =
                reinterpret_cast<const float4*>(Wm2 + k0 * DD)[lin];
        }
        __syncthreads();
#pragma unroll
        for (int kk = 0; kk < 16; kk++) {
            const int kg = k0 + kk;
            const ulonglong2 q0 = *reinterpret_cast<const ulonglong2*>(&Ws[kk * 256 + cA]);
            const ulonglong2 q1 = *reinterpret_cast<const ulonglong2*>(&Ws[kk * 256 + cB]);
#pragma unroll
            for (int r = 0; r < 8; r++) {
                const unsigned long long ad = dup2(Ts[(ty * 8 + r) * 260 + kg]);
                ffma2(acc[r][0], ad, q0.x);
                ffma2(acc[r][1], ad, q0.y);
                ffma2(acc[r][2], ad, q1.x);
                ffma2(acc[r][3], ad, q1.y);
            }
        }
        __syncthreads();
    }

    // ---- epilogue 2: + bm2, scatter-add into g_agg ----
    {
        const float4 bA = *reinterpret_cast<const float4*>(bm2 + cA);
        const float4 bB = *reinterpret_cast<const float4*>(bm2 + cB);
#pragma unroll
        for (int r = 0; r < 8; r++) {
            const int row = ty * 8 + r;
            const int dst = dst_s[row];
            const float2 v0 = up2(acc[r][0]), v1 = up2(acc[r][1]);
            const float2 v2 = up2(acc[r][2]), v3 = up2(acc[r][3]);
            const float4 oA = make_float4(v0.x + bA.x, v0.y + bA.y, v1.x + bA.z, v1.y + bA.w);
            const float4 oB = make_float4(v2.x + bB.x, v2.y + bB.y, v3.x + bB.z, v3.y + bB.w);
            red4(g_agg + dst * DD + cA, oA);
            red4(g_agg + dst * DD + cB, oB);
        }
    }
}

// out = relu(h0 @ Wr + br + agg), 32 nodes per block
__global__ void k_node(const float* __restrict__ Wr, const float* __restrict__ br) {
    __shared__ float As[32 * 256];  // 32 KB
    const int tid = threadIdx.x;
    const int tx = tid & 63;        // 64 col-groups of 4
    const int ty = tid >> 6;        // 4 row-groups of 8
    const int n0 = blockIdx.x * 32;
#pragma unroll
    for (int i = 0; i < 8; i++) {
        const int lin = i * 256 + tid;          // 2048 float4
        const int n = n0 + (lin >> 6);
        float4 v = make_float4(0.f, 0.f, 0.f, 0.f);
        if (n < N_NODES) v = reinterpret_cast<const float4*>(g_h0 + n * DD)[lin & 63];
        reinterpret_cast<float4*>(As)[lin] = v;
    }
    __syncthreads();
    const int c0 = tx * 4;
    unsigned long long acc[8][2];
#pragma unroll
    for (int r = 0; r < 8; r++) { acc[r][0] = 0ULL; acc[r][1] = 0ULL; }
    for (int k = 0; k < DD; k++) {
        const ulonglong2 w = *reinterpret_cast<const ulonglong2*>(Wr + k * DD + c0);
#pragma unroll
        for (int r = 0; r < 8; r++) {
            const unsigned long long a = dup2(As[(ty * 8 + r) * DD + k]);
            ffma2(acc[r][0], a, w.x);
            ffma2(acc[r][1], a, w.y);
        }
    }
    const float4 bb = *reinterpret_cast<const float4*>(br + c0);
#pragma unroll
    for (int r = 0; r < 8; r++) {
        const int n = n0 + ty * 8 + r;
        if (n >= N_NODES) break;
        const float4 ag = *reinterpret_cast<const float4*>(g_agg + n * DD + c0);
        const float2 v0 = up2(acc[r][0]), v1 = up2(acc[r][1]);
        const float4 o = make_float4(fmaxf(v0.x + bb.x + ag.x, 0.f),
                                     fmaxf(v0.y + bb.y + ag.y, 0.f),
                                     fmaxf(v1.x + bb.z + ag.z, 0.f),
                                     fmaxf(v1.y + bb.w + ag.w, 0.f));
        *reinterpret_cast<float4*>(g_out + n * DD + c0) = o;
    }
}

// gates = [qstar | h] @ [Wih ; Whh] + bl   (8 graphs per block)
__global__ void k_gates(const float* __restrict__ Wih, const float* __restrict__ Whh,
                        const float* __restrict__ bl) {
    __shared__ float As[8 * 768];   // 24 KB
    const int tid = threadIdx.x;
    const int b0 = blockIdx.x * 8;
    for (int i = tid; i < 8 * 768; i += 256) {
        const int r = i / 768, k = i - r * 768;
        As[i] = (k < 2 * DD) ? g_qstar[(b0 + r) * 2 * DD + k]
                             : g_h[(b0 + r) * DD + (k - 2 * DD)];
    }
    __syncthreads();
    const int j0 = tid * 4;
    unsigned long long acc[8][2];
#pragma unroll
    for (int r = 0; r < 8; r++) { acc[r][0] = 0ULL; acc[r][1] = 0ULL; }
    for (int k = 0; k < 2 * DD; k++) {
        const ulonglong2 w = *reinterpret_cast<const ulonglong2*>(Wih + k * 1024 + j0);
#pragma unroll
        for (int r = 0; r < 8; r++) {
            const unsigned long long a = dup2(As[r * 768 + k]);
            ffma2(acc[r][0], a, w.x);
            ffma2(acc[r][1], a, w.y);
        }
    }
    for (int k = 0; k < DD; k++) {
        const ulonglong2 w = *reinterpret_cast<const ulonglong2*>(Whh + k * 1024 + j0);
#pragma unroll
        for (int r = 0; r < 8; r++) {
            const unsigned long long a = dup2(As[r * 768 + 2 * DD + k]);
            ffma2(acc[r][0], a, w.x);
            ffma2(acc[r][1], a, w.y);
        }
    }
    const float4 bb = *reinterpret_cast<const float4*>(bl + j0);
#pragma unroll
    for (int r = 0; r < 8; r++) {
        const float2 v0 = up2(acc[r][0]), v1 = up2(acc[r][1]);
        const float4 o = make_float4(v0.x + bb.x, v0.y + bb.y, v1.x + bb.z, v1.y + bb.w);
        *reinterpret_cast<float4*>(g_gates + (b0 + r) * 1024 + j0) = o;
    }
}

__global__ void k_lstm() {
    const int b = blockIdx.x, d = threadIdx.x;
    const float* g = g_gates + b * 1024;
    const float i_ = g[d], f_ = g[DD + d], gg = g[2 * DD + d], o_ = g[3 * DD + d];
    const float c = sigm(f_) * g_c[b * DD + d] + sigm(i_) * tanhf(gg);
    const float h = sigm(o_) * tanhf(c);
    g_c[b * DD + d] = c;
    g_h[b * DD + d] = h;
}

// e[n] = dot(out[n], h[batch[n]]); one warp per node
__global__ void k_attn(const int* __restrict__ batch) {
    const int gi = blockIdx.x * blockDim.x + threadIdx.x;
    const int n = gi >> 5;
    const int lane = gi & 31;
    if (n >= N_NODES) return;
    const float4* o4 = reinterpret_cast<const float4*>(g_out + n * DD);
    const float4* h4 = reinterpret_cast<const float4*>(g_h + batch[n] * DD);
    float acc = 0.f;
#pragma unroll
    for (int i = 0; i < 2; i++) {
        const float4 a = o4[lane + i * 32];
        const float4 b = h4[lane + i * 32];
        acc = fmaf(a.x, b.x, acc);
        acc = fmaf(a.y, b.y, acc);
        acc = fmaf(a.z, b.z, acc);
        acc = fmaf(a.w, b.w, acc);
    }
#pragma unroll
    for (int o = 16; o > 0; o >>= 1) acc += __shfl_xor_sync(0xFFFFFFFFu, acc, o);
    if (lane == 0) g_e[n] = acc;
}

// segment softmax + weighted sum + write q_star = [h | r]; one block per graph
__global__ void k_pool() {
    __shared__ float red_[256];
    __shared__ float m_s, s_s;
    const int b = blockIdx.x, tid = threadIdx.x;
    const int s0 = g_start[b], s1 = g_start[b + 1];
    float r_acc = 0.f;
    if (s1 > s0) {
        float lm = -INFINITY;
        for (int n = s0 + tid; n < s1; n += 256) lm = fmaxf(lm, g_e[n]);
        red_[tid] = lm;
        __syncthreads();
        for (int o = 128; o > 0; o >>= 1) {
            if (tid < o) red_[tid] = fmaxf(red_[tid], red_[tid + o]);
            __syncthreads();
        }
        if (tid == 0) m_s = red_[0];
        __syncthreads();
        const float m = m_s;
        float ls = 0.f;
        for (int n = s0 + tid; n < s1; n += 256) ls += expf(g_e[n] - m);
        red_[tid] = ls;
        __syncthreads();
        for (int o = 128; o > 0; o >>= 1) {
            if (tid < o) red_[tid] += red_[tid + o];
            __syncthreads();
        }
        if (tid == 0) s_s = red_[0];
        __syncthreads();
        const float inv = 1.f / s_s;
        for (int n = s0; n < s1; n++) {
            const float w = expf(g_e[n] - m) * inv;
            r_acc = fmaf(w, g_out[n * DD + tid], r_acc);
        }
    }
    g_qstar[b * 2 * DD + tid] = g_h[b * DD + tid];
    g_qstar[b * 2 * DD + DD + tid] = r_acc;
}

// y = relu(qstar @ W1 + b1) @ W2 + b2; one block per graph
__global__ void k_readout(const float* __restrict__ W1, const float* __restrict__ b1,
                          const float* __restrict__ W2, const float* __restrict__ b2,
                          float* __restrict__ y) {
    __shared__ float q[2 * DD];
    __shared__ float red_[256];
    const int b = blockIdx.x, tid = threadIdx.x;
    q[tid] = g_qstar[b * 2 * DD + tid];
    q[DD + tid] = g_qstar[b * 2 * DD + DD + tid];
    __syncthreads();
    float acc = b1[tid];
    for (int k = 0; k < 2 * DD; k++) acc = fmaf(q[k], W1[k * DD + tid], acc);
    red_[tid] = fmaxf(acc, 0.f) * W2[tid];
    __syncthreads();
    for (int o = 128; o > 0; o >>= 1) {
        if (tid < o) red_[tid] += red_[tid + o];
        __syncthreads();
    }
    if (tid == 0) y[b] = red_[0] + b2[0];
}

// ---------------- launch ----------------
extern "C" void kernel_launch(void* const* d_in, const int* in_sizes, int n_in,
                              void* d_out, int out_size) {
    const float* x     = (const float*)d_in[0];
    const float* eattr = (const float*)d_in[1];
    const float* W0    = (const float*)d_in[2];
    const float* b0v   = (const float*)d_in[3];
    const float* Wm1   = (const float*)d_in[4];
    const float* bm1   = (const float*)d_in[5];
    const float* Wm2   = (const float*)d_in[6];
    const float* bm2   = (const float*)d_in[7];
    const float* Wr    = (const float*)d_in[8];
    const float* br    = (const float*)d_in[9];
    const float* Wih   = (const float*)d_in[10];
    const float* Whh   = (const float*)d_in[11];
    const float* bl    = (const float*)d_in[12];
    const float* W1    = (const float*)d_in[13];
    const float* b1    = (const float*)d_in[14];
    const float* W2    = (const float*)d_in[15];
    const float* b2    = (const float*)d_in[16];
    const int*   ei    = (const int*)d_in[17];
    const int*   batch = (const int*)d_in[18];

    // Unconditional (no static guards): idempotent, not a stream op, capture-safe.
    cudaFuncSetAttribute(k_edge, cudaFuncAttributeMaxDynamicSharedMemorySize, EDGE_SMEM);

    k_zero<<<256, 256>>>();
    k_offsets<<<(N_NODES + 255) / 256, 256>>>(batch);
    k_lin0<<<N_NODES / 16, 256>>>(x, W0, b0v);
    k_edge<<<N_EDGES / 64, 256, EDGE_SMEM>>>(eattr, Wm1, bm1, Wm2, bm2, ei);
    k_node<<<(N_NODES + 31) / 32, 256>>>(Wr, br);
    for (int s = 0; s < 3; s++) {
        k_gates<<<NG / 8, 256>>>(Wih, Whh, bl);
        k_lstm<<<NG, 256>>>();
        k_attn<<<(N_NODES * 32 + 255) / 256, 256>>>(batch);
        k_pool<<<NG, 256>>>();
    }
    k_readout<<<NG, 256>>>(W1, b1, W2, b2, (float*)d_out);
}

// round 13
// speedup vs baseline: 2.2614x; 2.2614x over previous
#include <cuda_runtime.h>
#include <cuda_fp16.h>
#include <math.h>
#include <stdint.h>

#define N_NODES 30000
#define N_EDGES 480000
#define FIN 25
#define FE   14
#define DD   256
#define NG   512

// ---------------- edge-mma kernel smem layout (bytes) ----------------
// src[64] ints | dst[64] ints | sA [64][296] half | sT [64][296] half | sB 2x[128][40] half
#define SO_SRC 0
#define SO_DST 256
#define SO_A   512
#define SO_T   (512 + 64 * 296 * 2)            // 38400
#define SO_B   (SO_T + 64 * 296 * 2)           // 76288
#define SB_BUF (128 * 40 * 2)                  // 10240
#define EM_SMEM (SO_B + 2 * SB_BUF)            // 96768

// ---------------- device scratch (no allocations allowed) ----------------
__device__ __align__(16) float g_h0[N_NODES * DD];
__device__ __align__(16) float g_agg[N_NODES * DD];
__device__ __align__(16) float g_out[N_NODES * DD];
__device__ __align__(16) float g_e[N_NODES];
__device__ __align__(16) float g_gates[NG * 4 * DD];
__device__ __align__(16) float g_h[NG * DD];
__device__ __align__(16) float g_c[NG * DD];
__device__ __align__(16) float g_qstar[NG * 2 * DD];
__device__ int g_start[NG + 1];
// fp16 tensors for mma path
__device__ __align__(16) __half g_h0h[N_NODES * DD];        // lin0 out, fp16
__device__ __align__(16) __half g_eah[N_EDGES * 16];        // eattr padded 14->16
__device__ __align__(16) __half g_W1T[256 * 320];           // Wm1^T [n][k], k padded 270->320
__device__ __align__(16) __half g_W2T[256 * 256];           // Wm2^T [n][k]

// ---------------- helpers ----------------
__device__ __forceinline__ void red2(float* p, float x, float y) {
    asm volatile("red.global.add.v2.f32 [%0], {%1, %2};"
                 :: "l"(p), "f"(x), "f"(y) : "memory");
}
__device__ __forceinline__ unsigned long long dup2(float v) {
    unsigned long long r;
    asm("mov.b64 %0, {%1, %1};" : "=l"(r) : "f"(v));
    return r;
}
__device__ __forceinline__ void ffma2(unsigned long long& d,
                                      unsigned long long a,
                                      unsigned long long b) {
    asm("fma.rn.f32x2 %0, %1, %2, %0;" : "+l"(d) : "l"(a), "l"(b));
}
__device__ __forceinline__ float2 up2(unsigned long long v) {
    float2 r;
    asm("mov.b64 {%0, %1}, %2;" : "=f"(r.x), "=f"(r.y) : "l"(v));
    return r;
}
__device__ __forceinline__ float sigm(float x) { return 1.f / (1.f + expf(-x)); }

__device__ __forceinline__ uint32_t smem_u32(const void* p) {
    uint32_t a;
    asm("{ .reg .u64 t; cvta.to.shared.u64 t, %1; cvt.u32.u64 %0, t; }"
        : "=r"(a) : "l"(p));
    return a;
}
__device__ __forceinline__ void ldm_x4(uint32_t* r, uint32_t addr) {
    asm volatile("ldmatrix.sync.aligned.m8n8.x4.shared.b16 {%0, %1, %2, %3}, [%4];"
                 : "=r"(r[0]), "=r"(r[1]), "=r"(r[2]), "=r"(r[3]) : "r"(addr));
}
__device__ __forceinline__ void hmma(float* d, const uint32_t* a,
                                     uint32_t b0, uint32_t b1) {
    asm volatile(
        "mma.sync.aligned.m16n8k16.row.col.f32.f16.f16.f32 "
        "{%0, %1, %2, %3}, {%4, %5, %6, %7}, {%8, %9}, {%0, %1, %2, %3};"
        : "+f"(d[0]), "+f"(d[1]), "+f"(d[2]), "+f"(d[3])
        : "r"(a[0]), "r"(a[1]), "r"(a[2]), "r"(a[3]), "r"(b0), "r"(b1));
}

// ---------------- kernels ----------------

__global__ void k_zero() {
    const int i = blockIdx.x * blockDim.x + threadIdx.x;
    const int stride = gridDim.x * blockDim.x;
    const float4 z = make_float4(0.f, 0.f, 0.f, 0.f);
    float4* agg4 = reinterpret_cast<float4*>(g_agg);
    for (int j = i; j < N_NODES * DD / 4; j += stride) agg4[j] = z;
    float4* h4 = reinterpret_cast<float4*>(g_h);
    float4* c4 = reinterpret_cast<float4*>(g_c);
    for (int j = i; j < NG * DD / 4; j += stride) { h4[j] = z; c4[j] = z; }
    float4* q4 = reinterpret_cast<float4*>(g_qstar);
    for (int j = i; j < NG * 2 * DD / 4; j += stride) q4[j] = z;
}

__global__ void k_offsets(const int* __restrict__ batch) {
    const int n = blockIdx.x * blockDim.x + threadIdx.x;
    if (n >= N_NODES) return;
    const int cur = batch[n];
    const int prev = (n == 0) ? -1 : batch[n - 1];
    for (int b = prev + 1; b <= cur; b++) g_start[b] = n;
    if (n == N_NODES - 1)
        for (int b = cur + 1; b <= NG; b++) g_start[b] = N_NODES;
}

// transpose weights to fp16 [n][k] layouts (B operands for mma.row.col)
__global__ void k_prepw(const float* __restrict__ Wm1, const float* __restrict__ Wm2) {
    const int i = blockIdx.x * 256 + threadIdx.x;
    if (i < 256 * 320) {
        const int n = i / 320, k = i - n * 320;
        g_W1T[i] = (k < 270) ? __float2half_rn(Wm1[k * 256 + n]) : __float2half_rn(0.f);
    }
    if (i < 256 * 256) {
        const int n = i >> 8, k = i & 255;
        g_W2T[i] = __float2half_rn(Wm2[k * 256 + n]);
    }
}

// eattr -> fp16, padded 14 -> 16
__global__ void k_prepea(const float* __restrict__ eattr) {
    const int i = blockIdx.x * 256 + threadIdx.x;
    if (i >= N_EDGES * 16) return;
    const int e = i >> 4, j = i & 15;
    g_eah[i] = (j < 14) ? __float2half_rn(eattr[e * 14 + j]) : __float2half_rn(0.f);
}

// h0 = relu(x @ W0 + b0); writes fp32 (k_node) and fp16 (mma)
__global__ void k_lin0(const float* __restrict__ x, const float* __restrict__ W0,
                       const float* __restrict__ b0v) {
    __shared__ float Ws[FIN * DD];
    __shared__ float xs[16][FIN + 1];
    const int tid = threadIdx.x;
    for (int i = tid; i < FIN * DD; i += 256) Ws[i] = W0[i];
    const int n0 = blockIdx.x * 16;
    for (int i = tid; i < 16 * FIN; i += 256) {
        const int r = i / FIN, c = i % FIN;
        const int n = n0 + r;
        xs[r][c] = (n < N_NODES) ? x[n * FIN + c] : 0.f;
    }
    __syncthreads();
    const float bb = b0v[tid];
#pragma unroll 4
    for (int r = 0; r < 16; r++) {
        const int n = n0 + r;
        if (n >= N_NODES) break;
        float acc = bb;
#pragma unroll
        for (int k = 0; k < FIN; k++) acc = fmaf(xs[r][k], Ws[k * DD + tid], acc);
        const float v = fmaxf(acc, 0.f);
        g_h0[n * DD + tid] = v;
        g_h0h[n * DD + tid] = __float2half_rn(v);
    }
}

// ---------------- mma.sync fused edge MLP ----------------
// 64 edges/CTA. GEMM1: [64,288]x[288,256]; relu; GEMM2: [64,256]x[256,256]; scatter.
// Warps: 2 (M, 32 rows) x 4 (N, 32 cols of current 128-col half).
__global__ void __launch_bounds__(256) k_edge_mma(const int* __restrict__ ei,
                                                  const float* __restrict__ bm1,
                                                  const float* __restrict__ bm2) {
    extern __shared__ char sm[];
    int* src_s = reinterpret_cast<int*>(sm + SO_SRC);
    int* dst_s = reinterpret_cast<int*>(sm + SO_DST);
    __half* sA = reinterpret_cast<__half*>(sm + SO_A);
    __half* sT = reinterpret_cast<__half*>(sm + SO_T);
    __half* sB = reinterpret_cast<__half*>(sm + SO_B);

    const int tid = threadIdx.x;
    const int wid = tid >> 5, lane = tid & 31;
    const int wr = wid >> 2;          // 0..1 : 32-row group
    const int wc = wid & 3;           // 0..3 : 32-col group within 128-half
    const int e0 = blockIdx.x * 64;

    if (tid < 64) src_s[tid] = ei[e0 + tid];
    else if (tid < 128) dst_s[tid - 64] = ei[N_EDGES + e0 + tid - 64];
    __syncthreads();

    // ---- stage A: [64 rows][296 halves], k0..255 = h0h[src], 256..271 = eattr, 272..287 = 0
#pragma unroll
    for (int j = 0; j < 9; j++) {
        const int i = j * 256 + tid;           // 0..2303
        const int r = i / 36, q = i - r * 36;  // 36 uint4 per row
        uint4 v = make_uint4(0, 0, 0, 0);
        if (q < 32)       v = *reinterpret_cast<const uint4*>(g_h0h + (size_t)src_s[r] * DD + q * 8);
        else if (q < 34)  v = *reinterpret_cast<const uint4*>(g_eah + (size_t)(e0 + r) * 16 + (q - 32) * 8);
        *reinterpret_cast<uint4*>(sA + r * 296 + q * 8) = v;
    }

    // per-thread ldmatrix bases
    const int lr = lane & 15, lk = lane >> 4;
    const uint32_t sA_u = smem_u32(sA);
    const uint32_t sT_u = smem_u32(sT);
    const uint32_t sB_u = smem_u32(sB);
    const uint32_t aA0 = sA_u + ((wr * 32 + lr) * 296 + lk * 8) * 2;
    const uint32_t aA1 = aA0 + 16 * 296 * 2;
    const uint32_t aT0 = sT_u + ((wr * 32 + lr) * 296 + lk * 8) * 2;
    const uint32_t aT1 = aT0 + 16 * 296 * 2;
    const uint32_t bOff = ((wc * 32 + lr) * 40 + lk * 8) * 2;

    const int g = lane >> 2, c2 = (lane & 3) * 2;

    float acc[2][4][4];

    // ================= GEMM1 (+ GEMM2 share this structure) =================
#pragma unroll 1
    for (int phase = 0; phase < 2; phase++) {
        const __half* Wsrc = phase == 0 ? g_W1T : g_W2T;
        const int wstride  = phase == 0 ? 320 : 256;
        const int nChunks  = phase == 0 ? 9 : 8;
        const uint32_t a0base = phase == 0 ? aA0 : aT0;
        const uint32_t a1base = phase == 0 ? aA1 : aT1;

#pragma unroll 1
        for (int nh = 0; nh < 2; nh++) {
#pragma unroll
            for (int mi = 0; mi < 2; mi++)
#pragma unroll
                for (int nj = 0; nj < 4; nj++)
#pragma unroll
                    for (int q = 0; q < 4; q++) acc[mi][nj][q] = 0.f;

            // stage chunk 0 into buf 0
            {
                const int i0 = tid, i1 = tid + 256;
                const int n0 = i0 >> 2, q0 = i0 & 3, n1 = i1 >> 2, q1 = i1 & 3;
                *reinterpret_cast<uint4*>(sB + n0 * 40 + q0 * 8) =
                    *reinterpret_cast<const uint4*>(Wsrc + (nh * 128 + n0) * wstride + q0 * 8);
                *reinterpret_cast<uint4*>(sB + n1 * 40 + q1 * 8) =
                    *reinterpret_cast<const uint4*>(Wsrc + (nh * 128 + n1) * wstride + q1 * 8);
            }
            __syncthreads();

#pragma unroll 1
            for (int kc = 0; kc < nChunks; kc++) {
                // prefetch next chunk into other buffer
                if (kc + 1 < nChunks) {
                    const int k0 = (kc + 1) * 32;
                    __half* dst = sB + ((kc + 1) & 1) * (SB_BUF / 2);
                    const int i0 = tid, i1 = tid + 256;
                    const int n0 = i0 >> 2, q0 = i0 & 3, n1 = i1 >> 2, q1 = i1 & 3;
                    *reinterpret_cast<uint4*>(dst + n0 * 40 + q0 * 8) =
                        *reinterpret_cast<const uint4*>(Wsrc + (nh * 128 + n0) * wstride + k0 + q0 * 8);
                    *reinterpret_cast<uint4*>(dst + n1 * 40 + q1 * 8) =
                        *reinterpret_cast<const uint4*>(Wsrc + (nh * 128 + n1) * wstride + k0 + q1 * 8);
                }
                const uint32_t bB = sB_u + (kc & 1) * SB_BUF + bOff;
#pragma unroll
                for (int s = 0; s < 2; s++) {
                    uint32_t a0[4], a1[4], b0[4], b1[4];
                    const uint32_t ak = (uint32_t)(kc * 32 + s * 16) * 2;
                    ldm_x4(a0, a0base + ak);
                    ldm_x4(a1, a1base + ak);
                    const uint32_t bk = (uint32_t)(s * 32);
                    ldm_x4(b0, bB + bk);
                    ldm_x4(b1, bB + 16 * 80 + bk);
                    hmma(acc[0][0], a0, b0[0], b0[2]);
                    hmma(acc[0][1], a0, b0[1], b0[3]);
                    hmma(acc[0][2], a0, b1[0], b1[2]);
                    hmma(acc[0][3], a0, b1[1], b1[3]);
                    hmma(acc[1][0], a1, b0[0], b0[2]);
                    hmma(acc[1][1], a1, b0[1], b0[3]);
                    hmma(acc[1][2], a1, b1[0], b1[2]);
                    hmma(acc[1][3], a1, b1[1], b1[3]);
                }
                __syncthreads();
            }

            if (phase == 0) {
                // epilogue 1: +bm1, relu, fp16 -> sT
#pragma unroll
                for (int mi = 0; mi < 2; mi++) {
                    const int r0 = wr * 32 + mi * 16 + g;
#pragma unroll
                    for (int nj = 0; nj < 4; nj++) {
                        const int col = nh * 128 + wc * 32 + nj * 8 + c2;
                        const float2 bb = *reinterpret_cast<const float2*>(bm1 + col);
                        const __half2 h01 = __floats2half2_rn(
                            fmaxf(acc[mi][nj][0] + bb.x, 0.f),
                            fmaxf(acc[mi][nj][1] + bb.y, 0.f));
                        const __half2 h23 = __floats2half2_rn(
                            fmaxf(acc[mi][nj][2] + bb.x, 0.f),
                            fmaxf(acc[mi][nj][3] + bb.y, 0.f));
                        *reinterpret_cast<__half2*>(sT + r0 * 296 + col) = h01;
                        *reinterpret_cast<__half2*>(sT + (r0 + 8) * 296 + col) = h23;
                    }
                }
            } else {
                // epilogue 2: +bm2, scatter-add into g_agg
#pragma unroll
                for (int mi = 0; mi < 2; mi++) {
                    const int r0 = wr * 32 + mi * 16 + g;
                    const int d0 = dst_s[r0], d1 = dst_s[r0 + 8];
#pragma unroll
                    for (int nj = 0; nj < 4; nj++) {
                        const int col = nh * 128 + wc * 32 + nj * 8 + c2;
                        const float2 bb = *reinterpret_cast<const float2*>(bm2 + col);
                        red2(g_agg + (size_t)d0 * DD + col,
                             acc[mi][nj][0] + bb.x, acc[mi][nj][1] + bb.y);
                        red2(g_agg + (size_t)d1 * DD + col,
                             acc[mi][nj][2] + bb.x, acc[mi][nj][3] + bb.y);
                    }
                }
            }
            __syncthreads();
        }
    }
}

// out = relu(h0 @ Wr + br + agg), 32 nodes per block
__global__ void k_node(const float* __restrict__ Wr, const float* __restrict__ br) {
    __shared__ float As[32 * 256];
    const int tid = threadIdx.x;
    const int tx = tid & 63;
    const int ty = tid >> 6;
    const int n0 = blockIdx.x * 32;
#pragma unroll
    for (int i = 0; i < 8; i++) {
        const int lin = i * 256 + tid;
        const int n = n0 + (lin >> 6);
        float4 v = make_float4(0.f, 0.f, 0.f, 0.f);
        if (n < N_NODES) v = reinterpret_cast<const float4*>(g_h0 + n * DD)[lin & 63];
        reinterpret_cast<float4*>(As)[lin] = v;
    }
    __syncthreads();
    const int c0 = tx * 4;
    unsigned long long acc[8][2];
#pragma unroll
    for (int r = 0; r < 8; r++) { acc[r][0] = 0ULL; acc[r][1] = 0ULL; }
    for (int k = 0; k < DD; k++) {
        const ulonglong2 w = *reinterpret_cast<const ulonglong2*>(Wr + k * DD + c0);
#pragma unroll
        for (int r = 0; r < 8; r++) {
            const unsigned long long a = dup2(As[(ty * 8 + r) * DD + k]);
            ffma2(acc[r][0], a, w.x);
            ffma2(acc[r][1], a, w.y);
        }
    }
    const float4 bb = *reinterpret_cast<const float4*>(br + c0);
#pragma unroll
    for (int r = 0; r < 8; r++) {
        const int n = n0 + ty * 8 + r;
        if (n >= N_NODES) break;
        const float4 ag = *reinterpret_cast<const float4*>(g_agg + n * DD + c0);
        const float2 v0 = up2(acc[r][0]), v1 = up2(acc[r][1]);
        const float4 o = make_float4(fmaxf(v0.x + bb.x + ag.x, 0.f),
                                     fmaxf(v0.y + bb.y + ag.y, 0.f),
                                     fmaxf(v1.x + bb.z + ag.z, 0.f),
                                     fmaxf(v1.y + bb.w + ag.w, 0.f));
        *reinterpret_cast<float4*>(g_out + n * DD + c0) = o;
    }
}

// gates = [qstar | h] @ [Wih ; Whh] + bl   (8 graphs per block)
__global__ void k_gates(const float* __restrict__ Wih, const float* __restrict__ Whh,
                        const float* __restrict__ bl) {
    __shared__ float As[8 * 768];
    const int tid = threadIdx.x;
    const int b0 = blockIdx.x * 8;
    for (int i = tid; i < 8 * 768; i += 256) {
        const int r = i / 768, k = i - r * 768;
        As[i] = (k < 2 * DD) ? g_qstar[(b0 + r) * 2 * DD + k]
                             : g_h[(b0 + r) * DD + (k - 2 * DD)];
    }
    __syncthreads();
    const int j0 = tid * 4;
    unsigned long long acc[8][2];
#pragma unroll
    for (int r = 0; r < 8; r++) { acc[r][0] = 0ULL; acc[r][1] = 0ULL; }
    for (int k = 0; k < 2 * DD; k++) {
        const ulonglong2 w = *reinterpret_cast<const ulonglong2*>(Wih + k * 1024 + j0);
#pragma unroll
        for (int r = 0; r < 8; r++) {
            const unsigned long long a = dup2(As[r * 768 + k]);
            ffma2(acc[r][0], a, w.x);
            ffma2(acc[r][1], a, w.y);
        }
    }
    for (int k = 0; k < DD; k++) {
        const ulonglong2 w = *reinterpret_cast<const ulonglong2*>(Whh + k * 1024 + j0);
#pragma unroll
        for (int r = 0; r < 8; r++) {
            const unsigned long long a = dup2(As[r * 768 + 2 * DD + k]);
            ffma2(acc[r][0], a, w.x);
            ffma2(acc[r][1], a, w.y);
        }
    }
    const float4 bb = *reinterpret_cast<const float4*>(bl + j0);
#pragma unroll
    for (int r = 0; r < 8; r++) {
        const float2 v0 = up2(acc[r][0]), v1 = up2(acc[r][1]);
        const float4 o = make_float4(v0.x + bb.x, v0.y + bb.y, v1.x + bb.z, v1.y + bb.w);
        *reinterpret_cast<float4*>(g_gates + (b0 + r) * 1024 + j0) = o;
    }
}

__global__ void k_lstm() {
    const int b = blockIdx.x, d = threadIdx.x;
    const float* g = g_gates + b * 1024;
    const float i_ = g[d], f_ = g[DD + d], gg = g[2 * DD + d], o_ = g[3 * DD + d];
    const float c = sigm(f_) * g_c[b * DD + d] + sigm(i_) * tanhf(gg);
    const float h = sigm(o_) * tanhf(c);
    g_c[b * DD + d] = c;
    g_h[b * DD + d] = h;
}

// e[n] = dot(out[n], h[batch[n]]); one warp per node
__global__ void k_attn(const int* __restrict__ batch) {
    const int gi = blockIdx.x * blockDim.x + threadIdx.x;
    const int n = gi >> 5;
    const int lane = gi & 31;
    if (n >= N_NODES) return;
    const float4* o4 = reinterpret_cast<const float4*>(g_out + n * DD);
    const float4* h4 = reinterpret_cast<const float4*>(g_h + batch[n] * DD);
    float acc = 0.f;
#pragma unroll
    for (int i = 0; i < 2; i++) {
        const float4 a = o4[lane + i * 32];
        const float4 b = h4[lane + i * 32];
        acc = fmaf(a.x, b.x, acc);
        acc = fmaf(a.y, b.y, acc);
        acc = fmaf(a.z, b.z, acc);
        acc = fmaf(a.w, b.w, acc);
    }
#pragma unroll
    for (int o = 16; o > 0; o >>= 1) acc += __shfl_xor_sync(0xFFFFFFFFu, acc, o);
    if (lane == 0) g_e[n] = acc;
}

// segment softmax + weighted sum + write q_star = [h | r]; one block per graph
__global__ void k_pool() {
    __shared__ float red_[256];
    __shared__ float m_s, s_s;
    const int b = blockIdx.x, tid = threadIdx.x;
    const int s0 = g_start[b], s1 = g_start[b + 1];
    float r_acc = 0.f;
    if (s1 > s0) {
        float lm = -INFINITY;
        for (int n = s0 + tid; n < s1; n += 256) lm = fmaxf(lm, g_e[n]);
        red_[tid] = lm;
        __syncthreads();
        for (int o = 128; o > 0; o >>= 1) {
            if (tid < o) red_[tid] = fmaxf(red_[tid], red_[tid + o]);
            __syncthreads();
        }
        if (tid == 0) m_s = red_[0];
        __syncthreads();
        const float m = m_s;
        float ls = 0.f;
        for (int n = s0 + tid; n < s1; n += 256) ls += expf(g_e[n] - m);
        red_[tid] = ls;
        __syncthreads();
        for (int o = 128; o > 0; o >>= 1) {
            if (tid < o) red_[tid] += red_[tid + o];
            __syncthreads();
        }
        if (tid == 0) s_s = red_[0];
        __syncthreads();
        const float inv = 1.f / s_s;
        for (int n = s0; n < s1; n++) {
            const float w = expf(g_e[n] - m) * inv;
            r_acc = fmaf(w, g_out[n * DD + tid], r_acc);
        }
    }
    g_qstar[b * 2 * DD + tid] = g_h[b * DD + tid];
    g_qstar[b * 2 * DD + DD + tid] = r_acc;
}

// y = relu(qstar @ W1 + b1) @ W2 + b2; one block per graph
__global__ void k_readout(const float* __restrict__ W1, const float* __restrict__ b1,
                          const float* __restrict__ W2, const float* __restrict__ b2,
                          float* __restrict__ y) {
    __shared__ float q[2 * DD];
    __shared__ float red_[256];
    const int b = blockIdx.x, tid = threadIdx.x;
    q[tid] = g_qstar[b * 2 * DD + tid];
    q[DD + tid] = g_qstar[b * 2 * DD + DD + tid];
    __syncthreads();
    float acc = b1[tid];
    for (int k = 0; k < 2 * DD; k++) acc = fmaf(q[k], W1[k * DD + tid], acc);
    red_[tid] = fmaxf(acc, 0.f) * W2[tid];
    __syncthreads();
    for (int o = 128; o > 0; o >>= 1) {
        if (tid < o) red_[tid] += red_[tid + o];
        __syncthreads();
    }
    if (tid == 0) y[b] = red_[0] + b2[0];
}

// ---------------- launch ----------------
extern "C" void kernel_launch(void* const* d_in, const int* in_sizes, int n_in,
                              void* d_out, int out_size) {
    const float* x     = (const float*)d_in[0];
    const float* eattr = (const float*)d_in[1];
    const float* W0    = (const float*)d_in[2];
    const float* b0v   = (const float*)d_in[3];
    const float* Wm1   = (const float*)d_in[4];
    const float* bm1   = (const float*)d_in[5];
    const float* Wm2   = (const float*)d_in[6];
    const float* bm2   = (const float*)d_in[7];
    const float* Wr    = (const float*)d_in[8];
    const float* br    = (const float*)d_in[9];
    const float* Wih   = (const float*)d_in[10];
    const float* Whh   = (const float*)d_in[11];
    const float* bl    = (const float*)d_in[12];
    const float* W1    = (const float*)d_in[13];
    const float* b1    = (const float*)d_in[14];
    const float* W2    = (const float*)d_in[15];
    const float* b2    = (const float*)d_in[16];
    const int*   ei    = (const int*)d_in[17];
    const int*   batch = (const int*)d_in[18];

    // Idempotent, capture-safe, no static guards.
    cudaFuncSetAttribute(k_edge_mma, cudaFuncAttributeMaxDynamicSharedMemorySize, EM_SMEM);

    k_zero<<<256, 256>>>();
    k_offsets<<<(N_NODES + 255) / 256, 256>>>(batch);
    k_prepw<<<320, 256>>>(Wm1, Wm2);
    k_prepea<<<(N_EDGES * 16 + 255) / 256, 256>>>(eattr);
    k_lin0<<<N_NODES / 16, 256>>>(x, W0, b0v);
    k_edge_mma<<<N_EDGES / 64, 256, EM_SMEM>>>(ei, bm1, bm2);
    k_node<<<(N_NODES + 31) / 32, 256>>>(Wr, br);
    for (int s = 0; s < 3; s++) {
        k_gates<<<NG / 8, 256>>>(Wih, Whh, bl);
        k_lstm<<<NG, 256>>>();
        k_attn<<<(N_NODES * 32 + 255) / 256, 256>>>(batch);
        k_pool<<<NG, 256>>>();
    }
    k_readout<<<NG, 256>>>(W1, b1, W2, b2, (float*)d_out);
}

// round 14
// speedup vs baseline: 2.4467x; 1.0819x over previous
#include <cuda_runtime.h>
#include <cuda_fp16.h>
#include <math.h>
#include <stdint.h>

#define N_NODES 30000
#define N_EDGES 480000
#define FIN 25
#define FE   14
#define DD   256
#define NG   512

// ---------------- edge-mma kernel smem layout (bytes) ----------------
// sA [128][296] half | sT [128][296] half | sB 2 x [128][40] half
#define SA_BYTES (128 * 296 * 2)               // 75776
#define SB_HALF  (128 * 40)                    // one buffer, halves
#define SO_T     SA_BYTES
#define SO_B     (2 * SA_BYTES)                // 151552
#define EM_SMEM  (SO_B + 2 * SB_HALF * 2)      // 172032

// ---------------- device scratch (no allocations allowed) ----------------
__device__ __align__(16) float g_h0[N_NODES * DD];
__device__ __align__(16) float g_agg[N_NODES * DD];
__device__ __align__(16) float g_out[N_NODES * DD];
__device__ __align__(16) float g_e[N_NODES];
__device__ __align__(16) float g_h[NG * DD];
__device__ __align__(16) float g_c[NG * DD];
__device__ __align__(16) float g_qstar[NG * 2 * DD];
__device__ int g_start[NG + 1];
// fp16 tensors for mma path
__device__ __align__(16) __half g_h0h[N_NODES * DD];        // lin0 out, fp16
__device__ __align__(16) __half g_eah[N_EDGES * 16];        // eattr padded 14->16
__device__ __align__(16) __half g_W1T[256 * 320];           // Wm1^T [n][k], k padded 270->320
__device__ __align__(16) __half g_W2T[256 * 256];           // Wm2^T [n][k]

// ---------------- helpers ----------------
__device__ __forceinline__ void red2(float* p, float x, float y) {
    asm volatile("red.global.add.v2.f32 [%0], {%1, %2};"
                 :: "l"(p), "f"(x), "f"(y) : "memory");
}
__device__ __forceinline__ unsigned long long dup2(float v) {
    unsigned long long r;
    asm("mov.b64 %0, {%1, %1};" : "=l"(r) : "f"(v));
    return r;
}
__device__ __forceinline__ void ffma2(unsigned long long& d,
                                      unsigned long long a,
                                      unsigned long long b) {
    asm("fma.rn.f32x2 %0, %1, %2, %0;" : "+l"(d) : "l"(a), "l"(b));
}
__device__ __forceinline__ float2 up2(unsigned long long v) {
    float2 r;
    asm("mov.b64 {%0, %1}, %2;" : "=f"(r.x), "=f"(r.y) : "l"(v));
    return r;
}
__device__ __forceinline__ float sigm(float x) { return 1.f / (1.f + expf(-x)); }

__device__ __forceinline__ uint32_t smem_u32(const void* p) {
    uint32_t a;
    asm("{ .reg .u64 t; cvta.to.shared.u64 t, %1; cvt.u32.u64 %0, t; }"
        : "=r"(a) : "l"(p));
    return a;
}
__device__ __forceinline__ void cpa16(uint32_t dst, const void* src) {
    asm volatile("cp.async.cg.shared.global [%0], [%1], 16;"
                 :: "r"(dst), "l"(src) : "memory");
}
__device__ __forceinline__ void cp_commit() {
    asm volatile("cp.async.commit_group;" ::: "memory");
}
template <int N>
__device__ __forceinline__ void cp_wait() {
    asm volatile("cp.async.wait_group %0;" :: "n"(N) : "memory");
}
__device__ __forceinline__ void ldm_x4(uint32_t* r, uint32_t addr) {
    asm volatile("ldmatrix.sync.aligned.m8n8.x4.shared.b16 {%0, %1, %2, %3}, [%4];"
                 : "=r"(r[0]), "=r"(r[1]), "=r"(r[2]), "=r"(r[3]) : "r"(addr));
}
__device__ __forceinline__ void hmma(float* d, const uint32_t* a,
                                     uint32_t b0, uint32_t b1) {
    asm volatile(
        "mma.sync.aligned.m16n8k16.row.col.f32.f16.f16.f32 "
        "{%0, %1, %2, %3}, {%4, %5, %6, %7}, {%8, %9}, {%0, %1, %2, %3};"
        : "+f"(d[0]), "+f"(d[1]), "+f"(d[2]), "+f"(d[3])
        : "r"(a[0]), "r"(a[1]), "r"(a[2]), "r"(a[3]), "r"(b0), "r"(b1));
}

// ---------------- kernels ----------------

__global__ void k_zero() {
    const int i = blockIdx.x * blockDim.x + threadIdx.x;
    const int stride = gridDim.x * blockDim.x;
    const float4 z = make_float4(0.f, 0.f, 0.f, 0.f);
    float4* agg4 = reinterpret_cast<float4*>(g_agg);
    for (int j = i; j < N_NODES * DD / 4; j += stride) agg4[j] = z;
    float4* h4 = reinterpret_cast<float4*>(g_h);
    float4* c4 = reinterpret_cast<float4*>(g_c);
    for (int j = i; j < NG * DD / 4; j += stride) { h4[j] = z; c4[j] = z; }
    float4* q4 = reinterpret_cast<float4*>(g_qstar);
    for (int j = i; j < NG * 2 * DD / 4; j += stride) q4[j] = z;
}

__global__ void k_offsets(const int* __restrict__ batch) {
    const int n = blockIdx.x * blockDim.x + threadIdx.x;
    if (n >= N_NODES) return;
    const int cur = batch[n];
    const int prev = (n == 0) ? -1 : batch[n - 1];
    for (int b = prev + 1; b <= cur; b++) g_start[b] = n;
    if (n == N_NODES - 1)
        for (int b = cur + 1; b <= NG; b++) g_start[b] = N_NODES;
}

// transpose weights to fp16 [n][k] layouts (B operands for mma.row.col)
__global__ void k_prepw(const float* __restrict__ Wm1, const float* __restrict__ Wm2) {
    const int i = blockIdx.x * 256 + threadIdx.x;
    if (i < 256 * 320) {
        const int n = i / 320, k = i - n * 320;
        g_W1T[i] = (k < 270) ? __float2half_rn(Wm1[k * 256 + n]) : __float2half_rn(0.f);
    }
    if (i < 256 * 256) {
        const int n = i >> 8, k = i & 255;
        g_W2T[i] = __float2half_rn(Wm2[k * 256 + n]);
    }
}

// eattr -> fp16 padded 14->16; 2 threads per edge, 16B coalesced writes
__global__ void k_prepea(const float* __restrict__ eattr) {
    const int t = blockIdx.x * 256 + threadIdx.x;
    if (t >= N_EDGES * 2) return;
    const int e = t >> 1, hf = t & 1;
    const float* src = eattr + (size_t)e * 14 + hf * 8;
    __half2 h[4];
    h[0] = __floats2half2_rn(src[0], src[1]);
    h[1] = __floats2half2_rn(src[2], src[3]);
    h[2] = __floats2half2_rn(src[4], src[5]);
    h[3] = hf ? __floats2half2_rn(0.f, 0.f) : __floats2half2_rn(src[6], src[7]);
    *reinterpret_cast<uint4*>(g_eah + (size_t)e * 16 + hf * 8) =
        *reinterpret_cast<const uint4*>(h);
}

// h0 = relu(x @ W0 + b0); writes fp32 (k_node) and fp16 (mma)
__global__ void k_lin0(const float* __restrict__ x, const float* __restrict__ W0,
                       const float* __restrict__ b0v) {
    __shared__ float Ws[FIN * DD];
    __shared__ float xs[16][FIN + 1];
    const int tid = threadIdx.x;
    for (int i = tid; i < FIN * DD; i += 256) Ws[i] = W0[i];
    const int n0 = blockIdx.x * 16;
    for (int i = tid; i < 16 * FIN; i += 256) {
        const int r = i / FIN, c = i % FIN;
        const int n = n0 + r;
        xs[r][c] = (n < N_NODES) ? x[n * FIN + c] : 0.f;
    }
    __syncthreads();
    const float bb = b0v[tid];
#pragma unroll 4
    for (int r = 0; r < 16; r++) {
        const int n = n0 + r;
        if (n >= N_NODES) break;
        float acc = bb;
#pragma unroll
        for (int k = 0; k < FIN; k++) acc = fmaf(xs[r][k], Ws[k * DD + tid], acc);
        const float v = fmaxf(acc, 0.f);
        g_h0[n * DD + tid] = v;
        g_h0h[n * DD + tid] = __float2half_rn(v);
    }
}

// ---------------- mma.sync fused edge MLP, 128 edges/CTA, cp.async pipeline ----------------
// GEMM1: [128,288]x[288,256]; relu -> sT; GEMM2: [128,256]x[256,256]; scatter-add.
// 8 warps: wr = wid>>1 (4 x 32-row groups), wc = wid&1 (2 x 64-col groups per 128-col half).
__global__ void __launch_bounds__(256) k_edge_mma(const int* __restrict__ ei,
                                                  const float* __restrict__ bm1,
                                                  const float* __restrict__ bm2) {
    extern __shared__ char sm[];
    __half* sT = reinterpret_cast<__half*>(sm + SO_T);
    const uint32_t sA_u = smem_u32(sm);
    const uint32_t sT_u = sA_u + SO_T;
    const uint32_t sB_u = sA_u + SO_B;

    const int tid = threadIdx.x;
    const int wid = tid >> 5, lane = tid & 31;
    const int wr = wid >> 1, wc = wid & 1;
    const int e0 = blockIdx.x * 128;

    // ---- stage A via cp.async: [128 rows][296 halves]; k0..255 h0h[src], 256..271 ea, 272..287 zero
#pragma unroll
    for (int j = 0; j < 18; j++) {
        const int i = j * 256 + tid;           // 0..4607
        const int r = i / 36, q = i - r * 36;
        const uint32_t dst = sA_u + (uint32_t)(r * 296 + q * 8) * 2;
        if (q < 32)
            cpa16(dst, g_h0h + (size_t)__ldg(ei + e0 + r) * DD + q * 8);
        else if (q < 34)
            cpa16(dst, g_eah + (size_t)(e0 + r) * 16 + (q - 32) * 8);
        else
            *reinterpret_cast<uint4*>(sm + (size_t)(r * 296 + q * 8) * 2) = make_uint4(0, 0, 0, 0);
    }

    const int lr = lane & 15, lk = lane >> 4;
    const uint32_t aA = sA_u + (uint32_t)((wr * 32 + lr) * 296 + lk * 8) * 2;
    const uint32_t aT = sT_u + (uint32_t)((wr * 32 + lr) * 296 + lk * 8) * 2;
    const uint32_t bO = (uint32_t)((wc * 64 + lr) * 40 + lk * 8) * 2;
    const int g = lane >> 2, c2 = (lane & 3) * 2;

    float acc[2][8][4];

#pragma unroll 1
    for (int phase = 0; phase < 2; phase++) {
        const __half* Wsrc = phase ? g_W2T : g_W1T;
        const int wstr = phase ? 256 : 320;
        const int nCh = phase ? 8 : 9;
        const uint32_t aBase = phase ? aT : aA;

#pragma unroll 1
        for (int nh = 0; nh < 2; nh++) {
#pragma unroll
            for (int mi = 0; mi < 2; mi++)
#pragma unroll
                for (int nj = 0; nj < 8; nj++)
#pragma unroll
                    for (int q = 0; q < 4; q++) acc[mi][nj][q] = 0.f;

            const __half* Wnh = Wsrc + (size_t)nh * 128 * wstr;
            // stage chunk 0 (first commit also covers the A copies above)
            {
                const int i0 = tid, i1 = tid + 256;
                const int n0 = i0 >> 2, q0 = i0 & 3;
                const int n1 = i1 >> 2, q1 = i1 & 3;
                cpa16(sB_u + (uint32_t)(n0 * 40 + q0 * 8) * 2, Wnh + n0 * wstr + q0 * 8);
                cpa16(sB_u + (uint32_t)(n1 * 40 + q1 * 8) * 2, Wnh + n1 * wstr + q1 * 8);
                cp_commit();
            }

#pragma unroll 1
            for (int kc = 0; kc < nCh; kc++) {
                if (kc + 1 < nCh) {
                    const int k0 = (kc + 1) * 32;
                    const uint32_t db = sB_u + (uint32_t)(((kc + 1) & 1) * SB_HALF) * 2;
                    const int i0 = tid, i1 = tid + 256;
                    const int n0 = i0 >> 2, q0 = i0 & 3;
                    const int n1 = i1 >> 2, q1 = i1 & 3;
                    cpa16(db + (uint32_t)(n0 * 40 + q0 * 8) * 2, Wnh + n0 * wstr + k0 + q0 * 8);
                    cpa16(db + (uint32_t)(n1 * 40 + q1 * 8) * 2, Wnh + n1 * wstr + k0 + q1 * 8);
                    cp_commit();
                    cp_wait<1>();
                } else {
                    cp_wait<0>();
                }
                __syncthreads();

                const uint32_t bB = sB_u + (uint32_t)((kc & 1) * SB_HALF) * 2 + bO;
#pragma unroll
                for (int s = 0; s < 2; s++) {
                    uint32_t a0[4], a1[4], b[4][4];
                    const uint32_t ak = (uint32_t)(kc * 32 + s * 16) * 2;
                    ldm_x4(a0, aBase + ak);
                    ldm_x4(a1, aBase + ak + 16 * 296 * 2);
                    const uint32_t bk = (uint32_t)(s * 32);
#pragma unroll
                    for (int t = 0; t < 4; t++) ldm_x4(b[t], bB + t * 1280 + bk);
#pragma unroll
                    for (int t = 0; t < 4; t++) {
                        hmma(acc[0][t * 2],     a0, b[t][0], b[t][2]);
                        hmma(acc[0][t * 2 + 1], a0, b[t][1], b[t][3]);
                        hmma(acc[1][t * 2],     a1, b[t][0], b[t][2]);
                        hmma(acc[1][t * 2 + 1], a1, b[t][1], b[t][3]);
                    }
                }
                __syncthreads();
            }

            if (phase == 0) {
                // epilogue 1: +bm1, relu, fp16 -> sT
#pragma unroll
                for (int mi = 0; mi < 2; mi++) {
                    const int r0 = wr * 32 + mi * 16 + g;
#pragma unroll
                    for (int nj = 0; nj < 8; nj++) {
                        const int col = nh * 128 + wc * 64 + nj * 8 + c2;
                        const float2 bb = *reinterpret_cast<const float2*>(bm1 + col);
                        const __half2 h01 = __floats2half2_rn(
                            fmaxf(acc[mi][nj][0] + bb.x, 0.f),
                            fmaxf(acc[mi][nj][1] + bb.y, 0.f));
                        const __half2 h23 = __floats2half2_rn(
                            fmaxf(acc[mi][nj][2] + bb.x, 0.f),
                            fmaxf(acc[mi][nj][3] + bb.y, 0.f));
                        *reinterpret_cast<__half2*>(sT + r0 * 296 + col) = h01;
                        *reinterpret_cast<__half2*>(sT + (r0 + 8) * 296 + col) = h23;
                    }
                }
            } else {
                // epilogue 2: +bm2, scatter-add into g_agg
#pragma unroll
                for (int mi = 0; mi < 2; mi++) {
                    const int r0 = wr * 32 + mi * 16 + g;
                    const int d0 = __ldg(ei + N_EDGES + e0 + r0);
                    const int d1 = __ldg(ei + N_EDGES + e0 + r0 + 8);
#pragma unroll
                    for (int nj = 0; nj < 8; nj++) {
                        const int col = nh * 128 + wc * 64 + nj * 8 + c2;
                        const float2 bb = *reinterpret_cast<const float2*>(bm2 + col);
                        red2(g_agg + (size_t)d0 * DD + col,
                             acc[mi][nj][0] + bb.x, acc[mi][nj][1] + bb.y);
                        red2(g_agg + (size_t)d1 * DD + col,
                             acc[mi][nj][2] + bb.x, acc[mi][nj][3] + bb.y);
                    }
                }
            }
            __syncthreads();
        }
    }
}

// out = relu(h0 @ Wr + br + agg), 32 nodes per block
__global__ void k_node(const float* __restrict__ Wr, const float* __restrict__ br) {
    __shared__ float As[32 * 256];
    const int tid = threadIdx.x;
    const int tx = tid & 63;
    const int ty = tid >> 6;
    const int n0 = blockIdx.x * 32;
#pragma unroll
    for (int i = 0; i < 8; i++) {
        const int lin = i * 256 + tid;
        const int n = n0 + (lin >> 6);
        float4 v = make_float4(0.f, 0.f, 0.f, 0.f);
        if (n < N_NODES) v = reinterpret_cast<const float4*>(g_h0 + n * DD)[lin & 63];
        reinterpret_cast<float4*>(As)[lin] = v;
    }
    __syncthreads();
    const int c0 = tx * 4;
    unsigned long long acc[8][2];
#pragma unroll
    for (int r = 0; r < 8; r++) { acc[r][0] = 0ULL; acc[r][1] = 0ULL; }
    for (int k = 0; k < DD; k++) {
        const ulonglong2 w = *reinterpret_cast<const ulonglong2*>(Wr + k * DD + c0);
#pragma unroll
        for (int r = 0; r < 8; r++) {
            const unsigned long long a = dup2(As[(ty * 8 + r) * DD + k]);
            ffma2(acc[r][0], a, w.x);
            ffma2(acc[r][1], a, w.y);
        }
    }
    const float4 bb = *reinterpret_cast<const float4*>(br + c0);
#pragma unroll
    for (int r = 0; r < 8; r++) {
        const int n = n0 + ty * 8 + r;
        if (n >= N_NODES) break;
        const float4 ag = *reinterpret_cast<const float4*>(g_agg + n * DD + c0);
        const float2 v0 = up2(acc[r][0]), v1 = up2(acc[r][1]);
        const float4 o = make_float4(fmaxf(v0.x + bb.x + ag.x, 0.f),
                                     fmaxf(v0.y + bb.y + ag.y, 0.f),
                                     fmaxf(v1.x + bb.z + ag.z, 0.f),
                                     fmaxf(v1.y + bb.w + ag.w, 0.f));
        *reinterpret_cast<float4*>(g_out + n * DD + c0) = o;
    }
}

// gates = [qstar | h] @ [Wih ; Whh] + bl, then fused LSTM cell (8 graphs per block)
__global__ void k_gates(const float* __restrict__ Wih, const float* __restrict__ Whh,
                        const float* __restrict__ bl) {
    __shared__ float As[8 * 768];    // 24 KB
    __shared__ float Gs[8 * 1024];   // 32 KB
    const int tid = threadIdx.x;
    const int b0 = blockIdx.x * 8;
    for (int i = tid; i < 8 * 768; i += 256) {
        const int r = i / 768, k = i - r * 768;
        As[i] = (k < 2 * DD) ? g_qstar[(b0 + r) * 2 * DD + k]
                             : g_h[(b0 + r) * DD + (k - 2 * DD)];
    }
    __syncthreads();
    const int j0 = tid * 4;
    unsigned long long acc[8][2];
#pragma unroll
    for (int r = 0; r < 8; r++) { acc[r][0] = 0ULL; acc[r][1] = 0ULL; }
    for (int k = 0; k < 2 * DD; k++) {
        const ulonglong2 w = *reinterpret_cast<const ulonglong2*>(Wih + k * 1024 + j0);
#pragma unroll
        for (int r = 0; r < 8; r++) {
            const unsigned long long a = dup2(As[r * 768 + k]);
            ffma2(acc[r][0], a, w.x);
            ffma2(acc[r][1], a, w.y);
        }
    }
    for (int k = 0; k < DD; k++) {
        const ulonglong2 w = *reinterpret_cast<const ulonglong2*>(Whh + k * 1024 + j0);
#pragma unroll
        for (int r = 0; r < 8; r++) {
            const unsigned long long a = dup2(As[r * 768 + 2 * DD + k]);
            ffma2(acc[r][0], a, w.x);
            ffma2(acc[r][1], a, w.y);
        }
    }
    const float4 bb = *reinterpret_cast<const float4*>(bl + j0);
#pragma unroll
    for (int r = 0; r < 8; r++) {
        const float2 v0 = up2(acc[r][0]), v1 = up2(acc[r][1]);
        const float4 o = make_float4(v0.x + bb.x, v0.y + bb.y, v1.x + bb.z, v1.y + bb.w);
        *reinterpret_cast<float4*>(Gs + r * 1024 + j0) = o;
    }
    __syncthreads();
    // fused LSTM cell
#pragma unroll
    for (int j = 0; j < 8; j++) {
        const int it = j * 256 + tid;
        const int r = it >> 8, d = it & 255;
        const float* gg = Gs + r * 1024;
        const int b = b0 + r;
        const float i_ = gg[d], f_ = gg[256 + d], gv = gg[512 + d], o_ = gg[768 + d];
        const float c = sigm(f_) * g_c[b * DD + d] + sigm(i_) * tanhf(gv);
        const float h = sigm(o_) * tanhf(c);
        g_c[b * DD + d] = c;
        g_h[b * DD + d] = h;
    }
}

// e[n] = dot(out[n], h[batch[n]]); one warp per node
__global__ void k_attn(const int* __restrict__ batch) {
    const int gi = blockIdx.x * blockDim.x + threadIdx.x;
    const int n = gi >> 5;
    const int lane = gi & 31;
    if (n >= N_NODES) return;
    const float4* o4 = reinterpret_cast<const float4*>(g_out + n * DD);
    const float4* h4 = reinterpret_cast<const float4*>(g_h + batch[n] * DD);
    float acc = 0.f;
#pragma unroll
    for (int i = 0; i < 2; i++) {
        const float4 a = o4[lane + i * 32];
        const float4 b = h4[lane + i * 32];
        acc = fmaf(a.x, b.x, acc);
        acc = fmaf(a.y, b.y, acc);
        acc = fmaf(a.z, b.z, acc);
        acc = fmaf(a.w, b.w, acc);
    }
#pragma unroll
    for (int o = 16; o > 0; o >>= 1) acc += __shfl_xor_sync(0xFFFFFFFFu, acc, o);
    if (lane == 0) g_e[n] = acc;
}

// segment softmax + weighted sum + write q_star = [h | r]; one block per graph
__global__ void k_pool() {
    __shared__ float red_[256];
    __shared__ float m_s, s_s;
    const int b = blockIdx.x, tid = threadIdx.x;
    const int s0 = g_start[b], s1 = g_start[b + 1];
    float r_acc = 0.f;
    if (s1 > s0) {
        float lm = -INFINITY;
        for (int n = s0 + tid; n < s1; n += 256) lm = fmaxf(lm, g_e[n]);
        red_[tid] = lm;
        __syncthreads();
        for (int o = 128; o > 0; o >>= 1) {
            if (tid < o) red_[tid] = fmaxf(red_[tid], red_[tid + o]);
            __syncthreads();
        }
        if (tid == 0) m_s = red_[0];
        __syncthreads();
        const float m = m_s;
        float ls = 0.f;
        for (int n = s0 + tid; n < s1; n += 256) ls += expf(g_e[n] - m);
        red_[tid] = ls;
        __syncthreads();
        for (int o = 128; o > 0; o >>= 1) {
            if (tid < o) red_[tid] += red_[tid + o];
            __syncthreads();
        }
        if (tid == 0) s_s = red_[0];
        __syncthreads();
        const float inv = 1.f / s_s;
        for (int n = s0; n < s1; n++) {
            const float w = expf(g_e[n] - m) * inv;
            r_acc = fmaf(w, g_out[n * DD + tid], r_acc);
        }
    }
    g_qstar[b * 2 * DD + tid] = g_h[b * DD + tid];
    g_qstar[b * 2 * DD + DD + tid] = r_acc;
}

// y = relu(qstar @ W1 + b1) @ W2 + b2; one block per graph
__global__ void k_readout(const float* __restrict__ W1, const float* __restrict__ b1,
                          const float* __restrict__ W2, const float* __restrict__ b2,
                          float* __restrict__ y) {
    __shared__ float q[2 * DD];
    __shared__ float red_[256];
    const int b = blockIdx.x, tid = threadIdx.x;
    q[tid] = g_qstar[b * 2 * DD + tid];
    q[DD + tid] = g_qstar[b * 2 * DD + DD + tid];
    __syncthreads();
    float acc = b1[tid];
    for (int k = 0; k < 2 * DD; k++) acc = fmaf(q[k], W1[k * DD + tid], acc);
    red_[tid] = fmaxf(acc, 0.f) * W2[tid];
    __syncthreads();
    for (int o = 128; o > 0; o >>= 1) {
        if (tid < o) red_[tid] += red_[tid + o];
        __syncthreads();
    }
    if (tid == 0) y[b] = red_[0] + b2[0];
}

// ---------------- launch ----------------
extern "C" void kernel_launch(void* const* d_in, const int* in_sizes, int n_in,
                              void* d_out, int out_size) {
    const float* x     = (const float*)d_in[0];
    const float* eattr = (const float*)d_in[1];
    const float* W0    = (const float*)d_in[2];
    const float* b0v   = (const float*)d_in[3];
    const float* Wm1   = (const float*)d_in[4];
    const float* bm1   = (const float*)d_in[5];
    const float* Wm2   = (const float*)d_in[6];
    const float* bm2   = (const float*)d_in[7];
    const float* Wr    = (const float*)d_in[8];
    const float* br    = (const float*)d_in[9];
    const float* Wih   = (const float*)d_in[10];
    const float* Whh   = (const float*)d_in[11];
    const float* bl    = (const float*)d_in[12];
    const float* W1    = (const float*)d_in[13];
    const float* b1    = (const float*)d_in[14];
    const float* W2    = (const float*)d_in[15];
    const float* b2    = (const float*)d_in[16];
    const int*   ei    = (const int*)d_in[17];
    const int*   batch = (const int*)d_in[18];

    // Idempotent, capture-safe, no static guards.
    cudaFuncSetAttribute(k_edge_mma, cudaFuncAttributeMaxDynamicSharedMemorySize, EM_SMEM);

    k_zero<<<256, 256>>>();
    k_offsets<<<(N_NODES + 255) / 256, 256>>>(batch);
    k_prepw<<<320, 256>>>(Wm1, Wm2);
    k_prepea<<<(N_EDGES * 2 + 255) / 256, 256>>>(eattr);
    k_lin0<<<N_NODES / 16, 256>>>(x, W0, b0v);
    k_edge_mma<<<N_EDGES / 128, 256, EM_SMEM>>>(ei, bm1, bm2);
    k_node<<<(N_NODES + 31) / 32, 256>>>(Wr, br);
    for (int s = 0; s < 3; s++) {
        k_gates<<<NG / 8, 256>>>(Wih, Whh, bl);
        k_attn<<<(N_NODES * 32 + 255) / 256, 256>>>(batch);
        k_pool<<<NG, 256>>>();
    }
    k_readout<<<NG, 256>>>(W1, b1, W2, b2, (float*)d_out);
}

// round 16
// speedup vs baseline: 4.9265x; 2.0136x over previous
#include <cuda_runtime.h>
#include <cuda_fp16.h>
#include <math.h>
#include <stdint.h>

#define N_NODES 30000
#define NPAD    30080              // 235 * 128
#define N_EDGES 480000
#define FIN 25
#define FE   14
#define DD   256
#define NG   512

// ---------------- device scratch (no allocations allowed) ----------------
__device__ __align__(16) float  g_P[NPAD * DD];      // h0 @ Wm1a (true cols)
__device__ __align__(16) float  g_S[NPAD * DD];      // sum of relu-messages per dst
__device__ __align__(16) float  g_out[NPAD * DD];
__device__ __align__(16) float  g_deg[NPAD];
__device__ __align__(16) float  g_e[N_NODES];
__device__ __align__(16) float  g_h[NG * DD];
__device__ __align__(16) float  g_c[NG * DD];
__device__ __align__(16) float  g_qstar[NG * 2 * DD];
__device__ int g_start[NG + 1];
__device__ __align__(16) __half g_h0h[NPAD * DD];    // lin0 out, fp16
__device__ __align__(16) __half g_Sh[NPAD * DD];     // fp16 copy of S
__device__ __align__(16) __half g_eah[N_EDGES * 16]; // eattr padded 14->16
__device__ __align__(16) __half g_W1aT[256 * 256];   // Wm1[0:256]^T, N-perm
__device__ __align__(16) __half g_W1eT[256 * 16];    // Wm1[256:270]^T, N-perm, k pad 16
__device__ __align__(16) __half g_WcatT[256 * 512];  // [Wr;Wm2]^T, N-perm

// ---------------- helpers ----------------
__device__ __forceinline__ void red4(float* p, float4 v) {
    asm volatile("red.global.add.v4.f32 [%0], {%1, %2, %3, %4};"
                 :: "l"(p), "f"(v.x), "f"(v.y), "f"(v.z), "f"(v.w) : "memory");
}
__device__ __forceinline__ void red1(float* p, float v) {
    asm volatile("red.global.add.f32 [%0], %1;" :: "l"(p), "f"(v) : "memory");
}
__device__ __forceinline__ unsigned long long dup2(float v) {
    unsigned long long r;
    asm("mov.b64 %0, {%1, %1};" : "=l"(r) : "f"(v));
    return r;
}
__device__ __forceinline__ void ffma2(unsigned long long& d,
                                      unsigned long long a,
                                      unsigned long long b) {
    asm("fma.rn.f32x2 %0, %1, %2, %0;" : "+l"(d) : "l"(a), "l"(b));
}
__device__ __forceinline__ float2 up2(unsigned long long v) {
    float2 r;
    asm("mov.b64 {%0, %1}, %2;" : "=f"(r.x), "=f"(r.y) : "l"(v));
    return r;
}
__device__ __forceinline__ float sigm(float x) { return 1.f / (1.f + expf(-x)); }

__device__ __forceinline__ uint32_t smem_u32(const void* p) {
    uint32_t a;
    asm("{ .reg .u64 t; cvta.to.shared.u64 t, %1; cvt.u32.u64 %0, t; }"
        : "=r"(a) : "l"(p));
    return a;
}
__device__ __forceinline__ void cpa16(uint32_t dst, const void* src) {
    asm volatile("cp.async.cg.shared.global [%0], [%1], 16;"
                 :: "r"(dst), "l"(src) : "memory");
}
__device__ __forceinline__ void cp_commit() {
    asm volatile("cp.async.commit_group;" ::: "memory");
}
template <int N>
__device__ __forceinline__ void cp_wait() {
    asm volatile("cp.async.wait_group %0;" :: "n"(N) : "memory");
}
__device__ __forceinline__ void ldm_x4(uint32_t* r, uint32_t addr) {
    asm volatile("ldmatrix.sync.aligned.m8n8.x4.shared.b16 {%0, %1, %2, %3}, [%4];"
                 : "=r"(r[0]), "=r"(r[1]), "=r"(r[2]), "=r"(r[3]) : "r"(addr));
}
__device__ __forceinline__ void hmma(float* d, const uint32_t* a,
                                     uint32_t b0, uint32_t b1) {
    asm volatile(
        "mma.sync.aligned.m16n8k16.row.col.f32.f16.f16.f32 "
        "{%0, %1, %2, %3}, {%4, %5, %6, %7}, {%8, %9}, {%0, %1, %2, %3};"
        : "+f"(d[0]), "+f"(d[1]), "+f"(d[2]), "+f"(d[3])
        : "r"(a[0]), "r"(a[1]), "r"(a[2]), "r"(a[3]), "r"(b0), "r"(b1));
}
// N-permutation: mma column n -> true memory column, so that each mma thread's
// 4 accumulator lanes are contiguous true columns (float4 epilogues).
__device__ __forceinline__ int nmap(int n) {
    const int t = n & ~15, r = n & 15, sub = (r >> 3) & 1, c = r & 7;
    return t + ((c >> 1) << 2) + (sub << 1) + (c & 1);
}

// ---------------- kernels ----------------

__global__ void k_zero() {
    const int i = blockIdx.x * blockDim.x + threadIdx.x;
    const int stride = gridDim.x * blockDim.x;
    const float4 z = make_float4(0.f, 0.f, 0.f, 0.f);
    float4* s4 = reinterpret_cast<float4*>(g_S);
    for (int j = i; j < NPAD * DD / 4; j += stride) s4[j] = z;
    float4* d4 = reinterpret_cast<float4*>(g_deg);
    for (int j = i; j < NPAD / 4; j += stride) d4[j] = z;
    float4* h4 = reinterpret_cast<float4*>(g_h);
    float4* c4 = reinterpret_cast<float4*>(g_c);
    for (int j = i; j < NG * DD / 4; j += stride) { h4[j] = z; c4[j] = z; }
    float4* q4 = reinterpret_cast<float4*>(g_qstar);
    for (int j = i; j < NG * 2 * DD / 4; j += stride) q4[j] = z;
}

__global__ void k_offsets(const int* __restrict__ batch) {
    const int n = blockIdx.x * blockDim.x + threadIdx.x;
    if (n >= N_NODES) return;
    const int cur = batch[n];
    const int prev = (n == 0) ? -1 : batch[n - 1];
    for (int b = prev + 1; b <= cur; b++) g_start[b] = n;
    if (n == N_NODES - 1)
        for (int b = cur + 1; b <= NG; b++) g_start[b] = N_NODES;
}

// fp16 N-permuted transposed weights
__global__ void k_prepw(const float* __restrict__ Wm1, const float* __restrict__ Wm2,
                        const float* __restrict__ Wr) {
    const int i = blockIdx.x * 256 + threadIdx.x;   // grid 512 -> 131072
    if (i < 256 * 256) {
        const int n = i >> 8, k = i & 255;
        g_W1aT[i] = __float2half_rn(Wm1[k * 256 + nmap(n)]);
    }
    if (i < 256 * 16) {
        const int n = i >> 4, k = i & 15;
        g_W1eT[i] = (k < 14) ? __float2half_rn(Wm1[(256 + k) * 256 + nmap(n)])
                             : __float2half_rn(0.f);
    }
    if (i < 256 * 512) {
        const int n = i >> 9, k = i & 511;
        g_WcatT[i] = (k < 256) ? __float2half_rn(Wr[k * 256 + nmap(n)])
                               : __float2half_rn(Wm2[(k - 256) * 256 + nmap(n)]);
    }
}

// eattr -> fp16 padded 14->16; 2 threads per edge, 16B coalesced writes
__global__ void k_prepea(const float* __restrict__ eattr) {
    const int t = blockIdx.x * 256 + threadIdx.x;
    if (t >= N_EDGES * 2) return;
    const int e = t >> 1, hf = t & 1;
    const float* src = eattr + (size_t)e * 14 + hf * 8;
    __half2 h[4];
    h[0] = __floats2half2_rn(src[0], src[1]);
    h[1] = __floats2half2_rn(src[2], src[3]);
    h[2] = __floats2half2_rn(src[4], src[5]);
    h[3] = hf ? __floats2half2_rn(0.f, 0.f) : __floats2half2_rn(src[6], src[7]);
    *reinterpret_cast<uint4*>(g_eah + (size_t)e * 16 + hf * 8) =
        *reinterpret_cast<const uint4*>(h);
}

// h0 = relu(x @ W0 + b0) -> fp16
__global__ void k_lin0(const float* __restrict__ x, const float* __restrict__ W0,
                       const float* __restrict__ b0v) {
    __shared__ float Ws[FIN * DD];
    __shared__ float xs[16][FIN + 1];
    const int tid = threadIdx.x;
    for (int i = tid; i < FIN * DD; i += 256) Ws[i] = W0[i];
    const int n0 = blockIdx.x * 16;
    for (int i = tid; i < 16 * FIN; i += 256) {
        const int r = i / FIN, c = i % FIN;
        const int n = n0 + r;
        xs[r][c] = (n < N_NODES) ? x[n * FIN + c] : 0.f;
    }
    __syncthreads();
    const float bb = b0v[tid];
#pragma unroll 4
    for (int r = 0; r < 16; r++) {
        const int n = n0 + r;
        if (n >= N_NODES) break;
        float acc = bb;
#pragma unroll
        for (int k = 0; k < FIN; k++) acc = fmaf(xs[r][k], Ws[k * DD + tid], acc);
        g_h0h[n * DD + tid] = __float2half_rn(fmaxf(acc, 0.f));
    }
}

// ---------------- node GEMM: 128x128 tile, K = 256 (MODE 0) or 512 (MODE 1) ----------------
// MODE 0: P = h0h @ W1aT                              -> g_P   (fp32, true cols)
// MODE 1: out = relu([h0h|Sh] @ WcatT + br + deg*bm2) -> g_out
template <int MODE>
__global__ void __launch_bounds__(256) k_ngemm(const float* __restrict__ br,
                                               const float* __restrict__ bm2) {
    constexpr int NCH = MODE ? 16 : 8;
    const __half* B = MODE ? g_WcatT : g_W1aT;
    const int KTOT = MODE ? 512 : 256;

    extern __shared__ char sm[];                 // 4 x 10240 B
    const uint32_t sAu = smem_u32(sm);
    const uint32_t sBu = sAu + 2 * 10240;

    const int tid = threadIdx.x;
    const int wid = tid >> 5, lane = tid & 31;
    const int wr = wid >> 1, wc = wid & 1;
    const int row0 = blockIdx.x * 128;
    const int ct = blockIdx.y;

    float acc[2][8][4];
#pragma unroll
    for (int mi = 0; mi < 2; mi++)
#pragma unroll
        for (int nj = 0; nj < 8; nj++)
#pragma unroll
            for (int q = 0; q < 4; q++) acc[mi][nj][q] = 0.f;

    // stage chunk 0
    {
        const uint32_t da = sAu, db = sBu;
#pragma unroll
        for (int it = 0; it < 2; it++) {
            const int idx = it * 256 + tid;      // 0..511
            const int r = idx >> 2, sg = idx & 3;
            const __half* asrc = g_h0h + (size_t)(row0 + r) * DD + sg * 8;
            cpa16(da + (uint32_t)(r * 40 + sg * 8) * 2, asrc);
            cpa16(db + (uint32_t)(r * 40 + sg * 8) * 2,
                  B + (size_t)(ct * 128 + r) * KTOT + sg * 8);
        }
        cp_commit();
    }

    const int lr = lane & 15, lk = lane >> 4;
    const int g = lane >> 2, q = lane & 3;

#pragma unroll 1
    for (int kc = 0; kc < NCH; kc++) {
        if (kc + 1 < NCH) {
            const int kn = kc + 1;
            const uint32_t da = sAu + (kn & 1) * 10240;
            const uint32_t db = sBu + (kn & 1) * 10240;
#pragma unroll
            for (int it = 0; it < 2; it++) {
                const int idx = it * 256 + tid;
                const int r = idx >> 2, sg = idx & 3;
                const __half* asrc =
                    (!MODE || kn < 8)
                        ? g_h0h + (size_t)(row0 + r) * DD + (kn & 7) * 32 + sg * 8
                        : g_Sh + (size_t)(row0 + r) * DD + (kn - 8) * 32 + sg * 8;
                cpa16(da + (uint32_t)(r * 40 + sg * 8) * 2, asrc);
                cpa16(db + (uint32_t)(r * 40 + sg * 8) * 2,
                      B + (size_t)(ct * 128 + r) * KTOT + kn * 32 + sg * 8);
            }
            cp_commit();
            cp_wait<1>();
        } else {
            cp_wait<0>();
        }
        __syncthreads();

        const uint32_t da = sAu + (kc & 1) * 10240;
        const uint32_t db = sBu + (kc & 1) * 10240;
#pragma unroll
        for (int s = 0; s < 2; s++) {
            uint32_t a0[4], a1[4];
            const uint32_t ko = (uint32_t)(s * 16 + lk * 8) * 2;
            ldm_x4(a0, da + (uint32_t)((wr * 32 + lr) * 40) * 2 + ko);
            ldm_x4(a1, da + (uint32_t)((wr * 32 + 16 + lr) * 40) * 2 + ko);
#pragma unroll
            for (int bn = 0; bn < 4; bn++) {
                uint32_t b[4];
                ldm_x4(b, db + (uint32_t)((wc * 64 + bn * 16 + lr) * 40) * 2 + ko);
                hmma(acc[0][bn * 2],     a0, b[0], b[2]);
                hmma(acc[0][bn * 2 + 1], a0, b[1], b[3]);
                hmma(acc[1][bn * 2],     a1, b[0], b[2]);
                hmma(acc[1][bn * 2 + 1], a1, b[1], b[3]);
            }
        }
        __syncthreads();
    }

    // epilogue (true cols contiguous thanks to nmap)
#pragma unroll
    for (int mi = 0; mi < 2; mi++) {
        const int r0 = row0 + wr * 32 + mi * 16 + g;
        const int r1 = r0 + 8;
#pragma unroll
        for (int t = 0; t < 4; t++) {
            const int tc = ct * 128 + wc * 64 + t * 16 + q * 4;
            float4 lo = make_float4(acc[mi][2 * t][0], acc[mi][2 * t][1],
                                    acc[mi][2 * t + 1][0], acc[mi][2 * t + 1][1]);
            float4 hi = make_float4(acc[mi][2 * t][2], acc[mi][2 * t][3],
                                    acc[mi][2 * t + 1][2], acc[mi][2 * t + 1][3]);
            if (MODE == 0) {
                *reinterpret_cast<float4*>(g_P + (size_t)r0 * DD + tc) = lo;
                *reinterpret_cast<float4*>(g_P + (size_t)r1 * DD + tc) = hi;
            } else {
                const float4 b1v = *reinterpret_cast<const float4*>(br + tc);
                const float4 b2v = *reinterpret_cast<const float4*>(bm2 + tc);
                const float d0 = g_deg[r0], d1 = g_deg[r1];
                lo.x = fmaxf(lo.x + b1v.x + d0 * b2v.x, 0.f);
                lo.y = fmaxf(lo.y + b1v.y + d0 * b2v.y, 0.f);
                lo.z = fmaxf(lo.z + b1v.z + d0 * b2v.z, 0.f);
                lo.w = fmaxf(lo.w + b1v.w + d0 * b2v.w, 0.f);
                hi.x = fmaxf(hi.x + b1v.x + d1 * b2v.x, 0.f);
                hi.y = fmaxf(hi.y + b1v.y + d1 * b2v.y, 0.f);
                hi.z = fmaxf(hi.z + b1v.z + d1 * b2v.z, 0.f);
                hi.w = fmaxf(hi.w + b1v.w + d1 * b2v.w, 0.f);
                *reinterpret_cast<float4*>(g_out + (size_t)r0 * DD + tc) = lo;
                *reinterpret_cast<float4*>(g_out + (size_t)r1 * DD + tc) = hi;
            }
        }
    }
}

// ---------------- edge kernel: t = relu(P[src] + ea@W1e + bm1); S[dst] += t ----------------
// 128 edges/CTA, K=16 single HMMA step; epilogue gathers P (float4) and red4 into S.
// SMEM row stride 24 halves = 48 B: 16-aligned for cp.async/ldmatrix, conflict-free.
__global__ void __launch_bounds__(256) k_edge2(const int* __restrict__ ei,
                                               const float* __restrict__ bm1) {
    __shared__ __half sEA[128 * 24];
    __shared__ __half sW[256 * 24];
    __shared__ int src_s[128], dst_s[128];

    const int tid = threadIdx.x;
    const int wid = tid >> 5, lane = tid & 31;
    const int wr = wid >> 1, wc = wid & 1;
    const int e0 = blockIdx.x * 128;

    if (tid < 128) src_s[tid] = ei[e0 + tid];
    else           dst_s[tid - 128] = ei[N_EDGES + e0 + tid - 128];
    {
        const int r = tid >> 1, hf = tid & 1;
        cpa16(smem_u32(sEA) + (uint32_t)(r * 24 + hf * 8) * 2,
              g_eah + (size_t)(e0 + r) * 16 + hf * 8);
    }
#pragma unroll
    for (int it = 0; it < 2; it++) {
        const int idx = it * 256 + tid;
        const int r = idx >> 1, hf = idx & 1;
        cpa16(smem_u32(sW) + (uint32_t)(r * 24 + hf * 8) * 2, g_W1eT + r * 16 + hf * 8);
    }
    cp_commit();
    cp_wait<0>();
    __syncthreads();

    const int lr = lane & 15, lk = lane >> 4;
    const int g = lane >> 2, q = lane & 3;
    uint32_t a0[4], a1[4];
    {
        const uint32_t ko = (uint32_t)(lk * 8) * 2;
        ldm_x4(a0, smem_u32(sEA) + (uint32_t)((wr * 32 + lr) * 24) * 2 + ko);
        ldm_x4(a1, smem_u32(sEA) + (uint32_t)((wr * 32 + 16 + lr) * 24) * 2 + ko);
    }

#pragma unroll
    for (int pass = 0; pass < 2; pass++) {
        const int colm = wc * 128 + pass * 64;
        float acc[2][8][4];
#pragma unroll
        for (int mi = 0; mi < 2; mi++)
#pragma unroll
            for (int nj = 0; nj < 8; nj++)
#pragma unroll
                for (int p = 0; p < 4; p++) acc[mi][nj][p] = 0.f;
#pragma unroll
        for (int bn = 0; bn < 4; bn++) {
            uint32_t b[4];
            ldm_x4(b, smem_u32(sW) + (uint32_t)((colm + bn * 16 + lr) * 24 + lk * 8) * 2);
            hmma(acc[0][bn * 2],     a0, b[0], b[2]);
            hmma(acc[0][bn * 2 + 1], a0, b[1], b[3]);
            hmma(acc[1][bn * 2],     a1, b[0], b[2]);
            hmma(acc[1][bn * 2 + 1], a1, b[1], b[3]);
        }
#pragma unroll
        for (int mi = 0; mi < 2; mi++) {
            const int r0 = wr * 32 + mi * 16 + g;
            const int r1 = r0 + 8;
            const int s0 = src_s[r0], s1 = src_s[r1];
            const int d0 = dst_s[r0], d1 = dst_s[r1];
#pragma unroll
            for (int t = 0; t < 4; t++) {
                const int tc = colm + t * 16 + q * 4;
                const float4 bb = *reinterpret_cast<const float4*>(bm1 + tc);
                const float4 p0 = *reinterpret_cast<const float4*>(g_P + (size_t)s0 * DD + tc);
                const float4 p1 = *reinterpret_cast<const float4*>(g_P + (size_t)s1 * DD + tc);
                float4 lo = make_float4(
                    fmaxf(acc[mi][2 * t][0] + p0.x + bb.x, 0.f),
                    fmaxf(acc[mi][2 * t][1] + p0.y + bb.y, 0.f),
                    fmaxf(acc[mi][2 * t + 1][0] + p0.z + bb.z, 0.f),
                    fmaxf(acc[mi][2 * t + 1][1] + p0.w + bb.w, 0.f));
                float4 hi = make_float4(
                    fmaxf(acc[mi][2 * t][2] + p1.x + bb.x, 0.f),
                    fmaxf(acc[mi][2 * t][3] + p1.y + bb.y, 0.f),
                    fmaxf(acc[mi][2 * t + 1][2] + p1.z + bb.z, 0.f),
                    fmaxf(acc[mi][2 * t + 1][3] + p1.w + bb.w, 0.f));
                red4(g_S + (size_t)d0 * DD + tc, lo);
                red4(g_S + (size_t)d1 * DD + tc, hi);
            }
        }
    }
    if (tid < 128) red1(g_deg + dst_s[tid], 1.f);
}

// S -> fp16
__global__ void k_cvtS() {
    const int i = (blockIdx.x * 256 + threadIdx.x) * 8;
    if (i >= NPAD * DD) return;
    const float4 a = *reinterpret_cast<const float4*>(g_S + i);
    const float4 b = *reinterpret_cast<const float4*>(g_S + i + 4);
    __half2 h[4];
    h[0] = __floats2half2_rn(a.x, a.y);
    h[1] = __floats2half2_rn(a.z, a.w);
    h[2] = __floats2half2_rn(b.x, b.y);
    h[3] = __floats2half2_rn(b.z, b.w);
    *reinterpret_cast<uint4*>(g_Sh + i) = *reinterpret_cast<const uint4*>(h);
}

// gates + fused LSTM cell (8 graphs per block)
__global__ void k_gates(const float* __restrict__ Wih, const float* __restrict__ Whh,
                        const float* __restrict__ bl) {
    __shared__ float As[8 * 768];
    __shared__ float Gs[8 * 1024];
    const int tid = threadIdx.x;
    const int b0 = blockIdx.x * 8;
    for (int i = tid; i < 8 * 768; i += 256) {
        const int r = i / 768, k = i - r * 768;
        As[i] = (k < 2 * DD) ? g_qstar[(b0 + r) * 2 * DD + k]
                             : g_h[(b0 + r) * DD + (k - 2 * DD)];
    }
    __syncthreads();
    const int j0 = tid * 4;
    unsigned long long acc[8][2];
#pragma unroll
    for (int r = 0; r < 8; r++) { acc[r][0] = 0ULL; acc[r][1] = 0ULL; }
    for (int k = 0; k < 2 * DD; k++) {
        const ulonglong2 w = *reinterpret_cast<const ulonglong2*>(Wih + k * 1024 + j0);
#pragma unroll
        for (int r = 0; r < 8; r++) {
            const unsigned long long a = dup2(As[r * 768 + k]);
            ffma2(acc[r][0], a, w.x);
            ffma2(acc[r][1], a, w.y);
        }
    }
    for (int k = 0; k < DD; k++) {
        const ulonglong2 w = *reinterpret_cast<const ulonglong2*>(Whh + k * 1024 + j0);
#pragma unroll
        for (int r = 0; r < 8; r++) {
            const unsigned long long a = dup2(As[r * 768 + 2 * DD + k]);
            ffma2(acc[r][0], a, w.x);
            ffma2(acc[r][1], a, w.y);
        }
    }
    const float4 bb = *reinterpret_cast<const float4*>(bl + j0);
#pragma unroll
    for (int r = 0; r < 8; r++) {
        const float2 v0 = up2(acc[r][0]), v1 = up2(acc[r][1]);
        const float4 o = make_float4(v0.x + bb.x, v0.y + bb.y, v1.x + bb.z, v1.y + bb.w);
        *reinterpret_cast<float4*>(Gs + r * 1024 + j0) = o;
    }
    __syncthreads();
#pragma unroll
    for (int j = 0; j < 8; j++) {
        const int it = j * 256 + tid;
        const int r = it >> 8, d = it & 255;
        const float* gg = Gs + r * 1024;
        const int b = b0 + r;
        const float i_ = gg[d], f_ = gg[256 + d], gv = gg[512 + d], o_ = gg[768 + d];
        const float c = sigm(f_) * g_c[b * DD + d] + sigm(i_) * tanhf(gv);
        const float h = sigm(o_) * tanhf(c);
        g_c[b * DD + d] = c;
        g_h[b * DD + d] = h;
    }
}

// e[n] = dot(out[n], h[batch[n]]); one warp per node
__global__ void k_attn(const int* __restrict__ batch) {
    const int gi = blockIdx.x * blockDim.x + threadIdx.x;
    const int n = gi >> 5;
    const int lane = gi & 31;
    if (n >= N_NODES) return;
    const float4* o4 = reinterpret_cast<const float4*>(g_out + (size_t)n * DD);
    const float4* h4 = reinterpret_cast<const float4*>(g_h + batch[n] * DD);
    float acc = 0.f;
#pragma unroll
    for (int i = 0; i < 2; i++) {
        const float4 a = o4[lane + i * 32];
        const float4 b = h4[lane + i * 32];
        acc = fmaf(a.x, b.x, acc);
        acc = fmaf(a.y, b.y, acc);
        acc = fmaf(a.z, b.z, acc);
        acc = fmaf(a.w, b.w, acc);
    }
#pragma unroll
    for (int o = 16; o > 0; o >>= 1) acc += __shfl_xor_sync(0xFFFFFFFFu, acc, o);
    if (lane == 0) g_e[n] = acc;
}

// segment softmax + weighted sum + write q_star = [h | r]; one block per graph
__global__ void k_pool() {
    __shared__ float red_[256];
    __shared__ float m_s, s_s;
    const int b = blockIdx.x, tid = threadIdx.x;
    const int s0 = g_start[b], s1 = g_start[b + 1];
    float r_acc = 0.f;
    if (s1 > s0) {
        float lm = -INFINITY;
        for (int n = s0 + tid; n < s1; n += 256) lm = fmaxf(lm, g_e[n]);
        red_[tid] = lm;
        __syncthreads();
        for (int o = 128; o > 0; o >>= 1) {
            if (tid < o) red_[tid] = fmaxf(red_[tid], red_[tid + o]);
            __syncthreads();
        }
        if (tid == 0) m_s = red_[0];
        __syncthreads();
        const float m = m_s;
        float ls = 0.f;
        for (int n = s0 + tid; n < s1; n += 256) ls += expf(g_e[n] - m);
        red_[tid] = ls;
        __syncthreads();
        for (int o = 128; o > 0; o >>= 1) {
            if (tid < o) red_[tid] += red_[tid + o];
            __syncthreads();
        }
        if (tid == 0) s_s = red_[0];
        __syncthreads();
        const float inv = 1.f / s_s;
        for (int n = s0; n < s1; n++) {
            const float w = expf(g_e[n] - m) * inv;
            r_acc = fmaf(w, g_out[(size_t)n * DD + tid], r_acc);
        }
    }
    g_qstar[b * 2 * DD + tid] = g_h[b * DD + tid];
    g_qstar[b * 2 * DD + DD + tid] = r_acc;
}

// y = relu(qstar @ W1 + b1) @ W2 + b2; one block per graph
__global__ void k_readout(const float* __restrict__ W1, const float* __restrict__ b1,
                          const float* __restrict__ W2, const float* __restrict__ b2,
                          float* __restrict__ y) {
    __shared__ float qv[2 * DD];
    __shared__ float red_[256];
    const int b = blockIdx.x, tid = threadIdx.x;
    qv[tid] = g_qstar[b * 2 * DD + tid];
    qv[DD + tid] = g_qstar[b * 2 * DD + DD + tid];
    __syncthreads();
    float acc = b1[tid];
    for (int k = 0; k < 2 * DD; k++) acc = fmaf(qv[k], W1[k * DD + tid], acc);
    red_[tid] = fmaxf(acc, 0.f) * W2[tid];
    __syncthreads();
    for (int o = 128; o > 0; o >>= 1) {
        if (tid < o) red_[tid] += red_[tid + o];
        __syncthreads();
    }
    if (tid == 0) y[b] = red_[0] + b2[0];
}

// ---------------- launch ----------------
extern "C" void kernel_launch(void* const* d_in, const int* in_sizes, int n_in,
                              void* d_out, int out_size) {
    const float* x     = (const float*)d_in[0];
    const float* eattr = (const float*)d_in[1];
    const float* W0    = (const float*)d_in[2];
    const float* b0v   = (const float*)d_in[3];
    const float* Wm1   = (const float*)d_in[4];
    const float* bm1   = (const float*)d_in[5];
    const float* Wm2   = (const float*)d_in[6];
    const float* bm2   = (const float*)d_in[7];
    const float* Wr    = (const float*)d_in[8];
    const float* br    = (const float*)d_in[9];
    const float* Wih   = (const float*)d_in[10];
    const float* Whh   = (const float*)d_in[11];
    const float* bl    = (const float*)d_in[12];
    const float* W1    = (const float*)d_in[13];
    const float* b1    = (const float*)d_in[14];
    const float* W2    = (const float*)d_in[15];
    const float* b2    = (const float*)d_in[16];
    const int*   ei    = (const int*)d_in[17];
    const int*   batch = (const int*)d_in[18];

    k_zero<<<256, 256>>>();
    k_offsets<<<(N_NODES + 255) / 256, 256>>>(batch);
    k_prepw<<<512, 256>>>(Wm1, Wm2, Wr);
    k_prepea<<<(N_EDGES * 2 + 255) / 256, 256>>>(eattr);
    k_lin0<<<(N_NODES + 15) / 16, 256>>>(x, W0, b0v);
    k_ngemm<0><<<dim3(NPAD / 128, 2), 256, 40960>>>(br, bm2);   // P
    k_edge2<<<N_EDGES / 128, 256>>>(ei, bm1);                   // S, deg
    k_cvtS<<<(NPAD * DD / 8 + 255) / 256, 256>>>();
    k_ngemm<1><<<dim3(NPAD / 128, 2), 256, 40960>>>(br, bm2);   // out
    for (int s = 0; s < 3; s++) {
        k_gates<<<NG / 8, 256>>>(Wih, Whh, bl);
        k_attn<<<(N_NODES * 32 + 255) / 256, 256>>>(batch);
        k_pool<<<NG, 256>>>();
    }
    k_readout<<<NG, 256>>>(W1, b1, W2, b2, (float*)d_out);
}

// round 17
// speedup vs baseline: 6.5549x; 1.3305x over previous
#include <cuda_runtime.h>
#include <cuda_fp16.h>
#include <math.h>
#include <stdint.h>

#define N_NODES 30000
#define NPAD    30080              // 235 * 128
#define N_EDGES 480000
#define FIN 25
#define FE   14
#define DD   256
#define NG   512

// ---------------- device scratch (no allocations allowed) ----------------
__device__ __align__(16) float  g_P[NPAD * DD];      // h0 @ Wm1a (true cols)
__device__ __align__(16) float  g_S[NPAD * DD];      // sum of relu-messages per dst
__device__ __align__(16) float  g_out[NPAD * DD];
__device__ __align__(16) float  g_deg[NPAD];
__device__ __align__(16) float  g_e[N_NODES];
__device__ __align__(16) float  g_h[NG * DD];
__device__ __align__(16) float  g_c[NG * DD];
__device__ __align__(16) float  g_qstar[NG * 2 * DD];
__device__ int g_start[NG + 1];
__device__ __align__(16) __half g_h0h[NPAD * DD];    // lin0 out, fp16
__device__ __align__(16) __half g_eah[N_EDGES * 16]; // eattr padded 14->16
__device__ __align__(16) __half g_W1aT[256 * 256];   // Wm1[0:256]^T, N-perm
__device__ __align__(16) __half g_W1eT[256 * 16];    // Wm1[256:270]^T, N-perm, k pad 16
__device__ __align__(16) __half g_WcatT[256 * 512];  // [Wr;Wm2]^T, N-perm
__device__ __align__(16) __half g_Wlh[768 * 1024];   // [Wih;Whh] fp16, [k][n]

// ---------------- helpers ----------------
__device__ __forceinline__ void red4(float* p, float4 v) {
    asm volatile("red.global.add.v4.f32 [%0], {%1, %2, %3, %4};"
                 :: "l"(p), "f"(v.x), "f"(v.y), "f"(v.z), "f"(v.w) : "memory");
}
__device__ __forceinline__ void red1(float* p, float v) {
    asm volatile("red.global.add.f32 [%0], %1;" :: "l"(p), "f"(v) : "memory");
}
__device__ __forceinline__ unsigned long long dup2(float v) {
    unsigned long long r;
    asm("mov.b64 %0, {%1, %1};" : "=l"(r) : "f"(v));
    return r;
}
__device__ __forceinline__ unsigned long long pk2(float x, float y) {
    unsigned long long r;
    asm("mov.b64 %0, {%1, %2};" : "=l"(r) : "f"(x), "f"(y));
    return r;
}
__device__ __forceinline__ void ffma2(unsigned long long& d,
                                      unsigned long long a,
                                      unsigned long long b) {
    asm("fma.rn.f32x2 %0, %1, %2, %0;" : "+l"(d) : "l"(a), "l"(b));
}
__device__ __forceinline__ float2 up2(unsigned long long v) {
    float2 r;
    asm("mov.b64 {%0, %1}, %2;" : "=f"(r.x), "=f"(r.y) : "l"(v));
    return r;
}
__device__ __forceinline__ float sigm(float x) { return 1.f / (1.f + expf(-x)); }

__device__ __forceinline__ uint32_t smem_u32(const void* p) {
    uint32_t a;
    asm("{ .reg .u64 t; cvta.to.shared.u64 t, %1; cvt.u32.u64 %0, t; }"
        : "=r"(a) : "l"(p));
    return a;
}
__device__ __forceinline__ void cpa16(uint32_t dst, const void* src) {
    asm volatile("cp.async.cg.shared.global [%0], [%1], 16;"
                 :: "r"(dst), "l"(src) : "memory");
}
__device__ __forceinline__ void cp_commit() {
    asm volatile("cp.async.commit_group;" ::: "memory");
}
template <int N>
__device__ __forceinline__ void cp_wait() {
    asm volatile("cp.async.wait_group %0;" :: "n"(N) : "memory");
}
__device__ __forceinline__ void ldm_x4(uint32_t* r, uint32_t addr) {
    asm volatile("ldmatrix.sync.aligned.m8n8.x4.shared.b16 {%0, %1, %2, %3}, [%4];"
                 : "=r"(r[0]), "=r"(r[1]), "=r"(r[2]), "=r"(r[3]) : "r"(addr));
}
__device__ __forceinline__ void hmma(float* d, const uint32_t* a,
                                     uint32_t b0, uint32_t b1) {
    asm volatile(
        "mma.sync.aligned.m16n8k16.row.col.f32.f16.f16.f32 "
        "{%0, %1, %2, %3}, {%4, %5, %6, %7}, {%8, %9}, {%0, %1, %2, %3};"
        : "+f"(d[0]), "+f"(d[1]), "+f"(d[2]), "+f"(d[3])
        : "r"(a[0]), "r"(a[1]), "r"(a[2]), "r"(a[3]), "r"(b0), "r"(b1));
}
// N-permutation: mma column n -> true memory column (contiguous float4 epilogues)
__device__ __forceinline__ int nmap(int n) {
    const int t = n & ~15, r = n & 15, sub = (r >> 3) & 1, c = r & 7;
    return t + ((c >> 1) << 2) + (sub << 1) + (c & 1);
}

// ---------------- kernels ----------------

__global__ void k_zero() {
    const int i = blockIdx.x * blockDim.x + threadIdx.x;
    const int stride = gridDim.x * blockDim.x;
    const float4 z = make_float4(0.f, 0.f, 0.f, 0.f);
    float4* s4 = reinterpret_cast<float4*>(g_S);
    for (int j = i; j < NPAD * DD / 4; j += stride) s4[j] = z;
    float4* d4 = reinterpret_cast<float4*>(g_deg);
    for (int j = i; j < NPAD / 4; j += stride) d4[j] = z;
    float4* h4 = reinterpret_cast<float4*>(g_h);
    float4* c4 = reinterpret_cast<float4*>(g_c);
    for (int j = i; j < NG * DD / 4; j += stride) { h4[j] = z; c4[j] = z; }
    float4* q4 = reinterpret_cast<float4*>(g_qstar);
    for (int j = i; j < NG * 2 * DD / 4; j += stride) q4[j] = z;
}

__global__ void k_offsets(const int* __restrict__ batch) {
    const int n = blockIdx.x * blockDim.x + threadIdx.x;
    if (n >= N_NODES) return;
    const int cur = batch[n];
    const int prev = (n == 0) ? -1 : batch[n - 1];
    for (int b = prev + 1; b <= cur; b++) g_start[b] = n;
    if (n == N_NODES - 1)
        for (int b = cur + 1; b <= NG; b++) g_start[b] = N_NODES;
}

// fp16 weight preps (N-permuted for mma paths; plain [k][n] for LSTM)
__global__ void k_prepw(const float* __restrict__ Wm1, const float* __restrict__ Wm2,
                        const float* __restrict__ Wr, const float* __restrict__ Wih,
                        const float* __restrict__ Whh) {
    const int i = blockIdx.x * 256 + threadIdx.x;   // grid 3072 -> 786432
    if (i < 256 * 256) {
        const int n = i >> 8, k = i & 255;
        g_W1aT[i] = __float2half_rn(Wm1[k * 256 + nmap(n)]);
    }
    if (i < 256 * 16) {
        const int n = i >> 4, k = i & 15;
        g_W1eT[i] = (k < 14) ? __float2half_rn(Wm1[(256 + k) * 256 + nmap(n)])
                             : __float2half_rn(0.f);
    }
    if (i < 256 * 512) {
        const int n = i >> 9, k = i & 511;
        g_WcatT[i] = (k < 256) ? __float2half_rn(Wr[k * 256 + nmap(n)])
                               : __float2half_rn(Wm2[(k - 256) * 256 + nmap(n)]);
    }
    if (i < 768 * 1024) {
        const int k = i >> 10, n = i & 1023;
        g_Wlh[i] = __float2half_rn(k < 512 ? Wih[k * 1024 + n]
                                           : Whh[(k - 512) * 1024 + n]);
    }
}

// eattr -> fp16 padded 14->16; 2 threads per edge, 16B coalesced writes
__global__ void k_prepea(const float* __restrict__ eattr) {
    const int t = blockIdx.x * 256 + threadIdx.x;
    if (t >= N_EDGES * 2) return;
    const int e = t >> 1, hf = t & 1;
    const float* src = eattr + (size_t)e * 14 + hf * 8;
    __half2 h[4];
    h[0] = __floats2half2_rn(src[0], src[1]);
    h[1] = __floats2half2_rn(src[2], src[3]);
    h[2] = __floats2half2_rn(src[4], src[5]);
    h[3] = hf ? __floats2half2_rn(0.f, 0.f) : __floats2half2_rn(src[6], src[7]);
    *reinterpret_cast<uint4*>(g_eah + (size_t)e * 16 + hf * 8) =
        *reinterpret_cast<const uint4*>(h);
}

// h0 = relu(x @ W0 + b0) -> fp16
__global__ void k_lin0(const float* __restrict__ x, const float* __restrict__ W0,
                       const float* __restrict__ b0v) {
    __shared__ float Ws[FIN * DD];
    __shared__ float xs[16][FIN + 1];
    const int tid = threadIdx.x;
    for (int i = tid; i < FIN * DD; i += 256) Ws[i] = W0[i];
    const int n0 = blockIdx.x * 16;
    for (int i = tid; i < 16 * FIN; i += 256) {
        const int r = i / FIN, c = i % FIN;
        const int n = n0 + r;
        xs[r][c] = (n < N_NODES) ? x[n * FIN + c] : 0.f;
    }
    __syncthreads();
    const float bb = b0v[tid];
#pragma unroll 4
    for (int r = 0; r < 16; r++) {
        const int n = n0 + r;
        if (n >= N_NODES) break;
        float acc = bb;
#pragma unroll
        for (int k = 0; k < FIN; k++) acc = fmaf(xs[r][k], Ws[k * DD + tid], acc);
        g_h0h[n * DD + tid] = __float2half_rn(fmaxf(acc, 0.f));
    }
}

// ---------------- node GEMM: 128x128 tile, K = 256 (MODE 0) or 512 (MODE 1) ----------------
// MODE 0: P = h0h @ W1aT                              -> g_P   (fp32, true cols)
// MODE 1: out = relu([h0h|S] @ WcatT + br + deg*bm2)  -> g_out (S converted in staging)
template <int MODE>
__global__ void __launch_bounds__(256) k_ngemm(const float* __restrict__ br,
                                               const float* __restrict__ bm2) {
    constexpr int NCH = MODE ? 16 : 8;
    const __half* B = MODE ? g_WcatT : g_W1aT;
    const int KTOT = MODE ? 512 : 256;

    extern __shared__ char sm[];                 // 4 x 10240 B
    const uint32_t sAu = smem_u32(sm);
    const uint32_t sBu = sAu + 2 * 10240;

    const int tid = threadIdx.x;
    const int wid = tid >> 5, lane = tid & 31;
    const int wr = wid >> 1, wc = wid & 1;
    const int row0 = blockIdx.x * 128;
    const int ct = blockIdx.y;

    float acc[2][8][4];
#pragma unroll
    for (int mi = 0; mi < 2; mi++)
#pragma unroll
        for (int nj = 0; nj < 8; nj++)
#pragma unroll
            for (int q = 0; q < 4; q++) acc[mi][nj][q] = 0.f;

    // stage chunk 0
    {
        const uint32_t da = sAu, db = sBu;
#pragma unroll
        for (int it = 0; it < 2; it++) {
            const int idx = it * 256 + tid;      // 0..511
            const int r = idx >> 2, sg = idx & 3;
            const __half* asrc = g_h0h + (size_t)(row0 + r) * DD + sg * 8;
            cpa16(da + (uint32_t)(r * 40 + sg * 8) * 2, asrc);
            cpa16(db + (uint32_t)(r * 40 + sg * 8) * 2,
                  B + (size_t)(ct * 128 + r) * KTOT + sg * 8);
        }
        cp_commit();
    }

    const int lr = lane & 15, lk = lane >> 4;
    const int g = lane >> 2, q = lane & 3;

#pragma unroll 1
    for (int kc = 0; kc < NCH; kc++) {
        if (kc + 1 < NCH) {
            const int kn = kc + 1;
            const uint32_t da = sAu + (kn & 1) * 10240;
            const uint32_t db = sBu + (kn & 1) * 10240;
#pragma unroll
            for (int it = 0; it < 2; it++) {
                const int idx = it * 256 + tid;
                const int r = idx >> 2, sg = idx & 3;
                if (!MODE || kn < 8) {
                    const __half* asrc =
                        g_h0h + (size_t)(row0 + r) * DD + (kn & 7) * 32 + sg * 8;
                    cpa16(da + (uint32_t)(r * 40 + sg * 8) * 2, asrc);
                } else {
                    // S chunk: fp32 load + convert + STS (replaces k_cvtS)
                    const float* s = g_S + (size_t)(row0 + r) * DD + (kn - 8) * 32 + sg * 8;
                    const float4 a = *reinterpret_cast<const float4*>(s);
                    const float4 b = *reinterpret_cast<const float4*>(s + 4);
                    __half2 hh[4];
                    hh[0] = __floats2half2_rn(a.x, a.y);
                    hh[1] = __floats2half2_rn(a.z, a.w);
                    hh[2] = __floats2half2_rn(b.x, b.y);
                    hh[3] = __floats2half2_rn(b.z, b.w);
                    *reinterpret_cast<uint4*>(sm + (kn & 1) * 10240 +
                                              (size_t)(r * 40 + sg * 8) * 2) =
                        *reinterpret_cast<const uint4*>(hh);
                }
                cpa16(db + (uint32_t)(r * 40 + sg * 8) * 2,
                      B + (size_t)(ct * 128 + r) * KTOT + kn * 32 + sg * 8);
            }
            cp_commit();
            cp_wait<1>();
        } else {
            cp_wait<0>();
        }
        __syncthreads();

        const uint32_t da = sAu + (kc & 1) * 10240;
        const uint32_t db = sBu + (kc & 1) * 10240;
#pragma unroll
        for (int s = 0; s < 2; s++) {
            uint32_t a0[4], a1[4];
            const uint32_t ko = (uint32_t)(s * 16 + lk * 8) * 2;
            ldm_x4(a0, da + (uint32_t)((wr * 32 + lr) * 40) * 2 + ko);
            ldm_x4(a1, da + (uint32_t)((wr * 32 + 16 + lr) * 40) * 2 + ko);
#pragma unroll
            for (int bn = 0; bn < 4; bn++) {
                uint32_t b[4];
                ldm_x4(b, db + (uint32_t)((wc * 64 + bn * 16 + lr) * 40) * 2 + ko);
                hmma(acc[0][bn * 2],     a0, b[0], b[2]);
                hmma(acc[0][bn * 2 + 1], a0, b[1], b[3]);
                hmma(acc[1][bn * 2],     a1, b[0], b[2]);
                hmma(acc[1][bn * 2 + 1], a1, b[1], b[3]);
            }
        }
        __syncthreads();
    }

    // epilogue (true cols contiguous thanks to nmap)
#pragma unroll
    for (int mi = 0; mi < 2; mi++) {
        const int r0 = row0 + wr * 32 + mi * 16 + g;
        const int r1 = r0 + 8;
#pragma unroll
        for (int t = 0; t < 4; t++) {
            const int tc = ct * 128 + wc * 64 + t * 16 + q * 4;
            float4 lo = make_float4(acc[mi][2 * t][0], acc[mi][2 * t][1],
                                    acc[mi][2 * t + 1][0], acc[mi][2 * t + 1][1]);
            float4 hi = make_float4(acc[mi][2 * t][2], acc[mi][2 * t][3],
                                    acc[mi][2 * t + 1][2], acc[mi][2 * t + 1][3]);
            if (MODE == 0) {
                *reinterpret_cast<float4*>(g_P + (size_t)r0 * DD + tc) = lo;
                *reinterpret_cast<float4*>(g_P + (size_t)r1 * DD + tc) = hi;
            } else {
                const float4 b1v = *reinterpret_cast<const float4*>(br + tc);
                const float4 b2v = *reinterpret_cast<const float4*>(bm2 + tc);
                const float d0 = g_deg[r0], d1 = g_deg[r1];
                lo.x = fmaxf(lo.x + b1v.x + d0 * b2v.x, 0.f);
                lo.y = fmaxf(lo.y + b1v.y + d0 * b2v.y, 0.f);
                lo.z = fmaxf(lo.z + b1v.z + d0 * b2v.z, 0.f);
                lo.w = fmaxf(lo.w + b1v.w + d0 * b2v.w, 0.f);
                hi.x = fmaxf(hi.x + b1v.x + d1 * b2v.x, 0.f);
                hi.y = fmaxf(hi.y + b1v.y + d1 * b2v.y, 0.f);
                hi.z = fmaxf(hi.z + b1v.z + d1 * b2v.z, 0.f);
                hi.w = fmaxf(hi.w + b1v.w + d1 * b2v.w, 0.f);
                *reinterpret_cast<float4*>(g_out + (size_t)r0 * DD + tc) = lo;
                *reinterpret_cast<float4*>(g_out + (size_t)r1 * DD + tc) = hi;
            }
        }
    }
}

// ---------------- edge kernel: t = relu(P[src] + ea@W1e + bm1); S[dst] += t ----------------
__global__ void __launch_bounds__(256) k_edge2(const int* __restrict__ ei,
                                               const float* __restrict__ bm1) {
    __shared__ __half sEA[128 * 24];
    __shared__ __half sW[256 * 24];
    __shared__ int src_s[128], dst_s[128];

    const int tid = threadIdx.x;
    const int wid = tid >> 5, lane = tid & 31;
    const int wr = wid >> 1, wc = wid & 1;
    const int e0 = blockIdx.x * 128;

    if (tid < 128) src_s[tid] = ei[e0 + tid];
    else           dst_s[tid - 128] = ei[N_EDGES + e0 + tid - 128];
    {
        const int r = tid >> 1, hf = tid & 1;
        cpa16(smem_u32(sEA) + (uint32_t)(r * 24 + hf * 8) * 2,
              g_eah + (size_t)(e0 + r) * 16 + hf * 8);
    }
#pragma unroll
    for (int it = 0; it < 2; it++) {
        const int idx = it * 256 + tid;
        const int r = idx >> 1, hf = idx & 1;
        cpa16(smem_u32(sW) + (uint32_t)(r * 24 + hf * 8) * 2, g_W1eT + r * 16 + hf * 8);
    }
    cp_commit();
    cp_wait<0>();
    __syncthreads();

    const int lr = lane & 15, lk = lane >> 4;
    const int g = lane >> 2, q = lane & 3;
    uint32_t a0[4], a1[4];
    {
        const uint32_t ko = (uint32_t)(lk * 8) * 2;
        ldm_x4(a0, smem_u32(sEA) + (uint32_t)((wr * 32 + lr) * 24) * 2 + ko);
        ldm_x4(a1, smem_u32(sEA) + (uint32_t)((wr * 32 + 16 + lr) * 24) * 2 + ko);
    }

#pragma unroll
    for (int pass = 0; pass < 2; pass++) {
        const int colm = wc * 128 + pass * 64;
        float acc[2][8][4];
#pragma unroll
        for (int mi = 0; mi < 2; mi++)
#pragma unroll
            for (int nj = 0; nj < 8; nj++)
#pragma unroll
                for (int p = 0; p < 4; p++) acc[mi][nj][p] = 0.f;
#pragma unroll
        for (int bn = 0; bn < 4; bn++) {
            uint32_t b[4];
            ldm_x4(b, smem_u32(sW) + (uint32_t)((colm + bn * 16 + lr) * 24 + lk * 8) * 2);
            hmma(acc[0][bn * 2],     a0, b[0], b[2]);
            hmma(acc[0][bn * 2 + 1], a0, b[1], b[3]);
            hmma(acc[1][bn * 2],     a1, b[0], b[2]);
            hmma(acc[1][bn * 2 + 1], a1, b[1], b[3]);
        }
#pragma unroll
        for (int mi = 0; mi < 2; mi++) {
            const int r0 = wr * 32 + mi * 16 + g;
            const int r1 = r0 + 8;
            const int s0 = src_s[r0], s1 = src_s[r1];
            const int d0 = dst_s[r0], d1 = dst_s[r1];
#pragma unroll
            for (int t = 0; t < 4; t++) {
                const int tc = colm + t * 16 + q * 4;
                const float4 bb = *reinterpret_cast<const float4*>(bm1 + tc);
                const float4 p0 = *reinterpret_cast<const float4*>(g_P + (size_t)s0 * DD + tc);
                const float4 p1 = *reinterpret_cast<const float4*>(g_P + (size_t)s1 * DD + tc);
                float4 lo = make_float4(
                    fmaxf(acc[mi][2 * t][0] + p0.x + bb.x, 0.f),
                    fmaxf(acc[mi][2 * t][1] + p0.y + bb.y, 0.f),
                    fmaxf(acc[mi][2 * t + 1][0] + p0.z + bb.z, 0.f),
                    fmaxf(acc[mi][2 * t + 1][1] + p0.w + bb.w, 0.f));
                float4 hi = make_float4(
                    fmaxf(acc[mi][2 * t][2] + p1.x + bb.x, 0.f),
                    fmaxf(acc[mi][2 * t][3] + p1.y + bb.y, 0.f),
                    fmaxf(acc[mi][2 * t + 1][2] + p1.z + bb.z, 0.f),
                    fmaxf(acc[mi][2 * t + 1][3] + p1.w + bb.w, 0.f));
                red4(g_S + (size_t)d0 * DD + tc, lo);
                red4(g_S + (size_t)d1 * DD + tc, hi);
            }
        }
    }
    if (tid < 128) red1(g_deg + dst_s[tid], 1.f);
}

// gates (fp16 weights) + fused LSTM cell; 4 graphs per block, 128 blocks
__global__ void k_gates(const float* __restrict__ bl) {
    __shared__ float As[4 * 768];    // 12 KB
    __shared__ float Gs[4 * 1024];   // 16 KB
    const int tid = threadIdx.x;
    const int b0 = blockIdx.x * 4;
    for (int i = tid; i < 4 * 768; i += 256) {
        const int r = i / 768, k = i - r * 768;
        As[i] = (k < 2 * DD) ? g_qstar[(b0 + r) * 2 * DD + k]
                             : g_h[(b0 + r) * DD + (k - 2 * DD)];
    }
    __syncthreads();
    const int j0 = tid * 4;
    unsigned long long acc[4][2];
#pragma unroll
    for (int r = 0; r < 4; r++) { acc[r][0] = 0ULL; acc[r][1] = 0ULL; }
    for (int k = 0; k < 768; k++) {
        const uint2 wv = *reinterpret_cast<const uint2*>(g_Wlh + (size_t)k * 1024 + j0);
        const __half2 h0 = *reinterpret_cast<const __half2*>(&wv.x);
        const __half2 h1 = *reinterpret_cast<const __half2*>(&wv.y);
        const float2 f0 = __half22float2(h0);
        const float2 f1 = __half22float2(h1);
        const unsigned long long w0 = pk2(f0.x, f0.y);
        const unsigned long long w1 = pk2(f1.x, f1.y);
#pragma unroll
        for (int r = 0; r < 4; r++) {
            const unsigned long long a = dup2(As[r * 768 + k]);
            ffma2(acc[r][0], a, w0);
            ffma2(acc[r][1], a, w1);
        }
    }
    const float4 bb = *reinterpret_cast<const float4*>(bl + j0);
#pragma unroll
    for (int r = 0; r < 4; r++) {
        const float2 v0 = up2(acc[r][0]), v1 = up2(acc[r][1]);
        const float4 o = make_float4(v0.x + bb.x, v0.y + bb.y, v1.x + bb.z, v1.y + bb.w);
        *reinterpret_cast<float4*>(Gs + r * 1024 + j0) = o;
    }
    __syncthreads();
    // fused LSTM cell: 4 graphs x 256 dims
#pragma unroll
    for (int j = 0; j < 4; j++) {
        const int it = j * 256 + tid;
        const int r = it >> 8, d = it & 255;
        const float* gg = Gs + r * 1024;
        const int b = b0 + r;
        const float i_ = gg[d], f_ = gg[256 + d], gv = gg[512 + d], o_ = gg[768 + d];
        const float c = sigm(f_) * g_c[b * DD + d] + sigm(i_) * tanhf(gv);
        const float h = sigm(o_) * tanhf(c);
        g_c[b * DD + d] = c;
        g_h[b * DD + d] = h;
    }
}

// e[n] = dot(out[n], h[batch[n]]); one warp per node
__global__ void k_attn(const int* __restrict__ batch) {
    const int gi = blockIdx.x * blockDim.x + threadIdx.x;
    const int n = gi >> 5;
    const int lane = gi & 31;
    if (n >= N_NODES) return;
    const float4* o4 = reinterpret_cast<const float4*>(g_out + (size_t)n * DD);
    const float4* h4 = reinterpret_cast<const float4*>(g_h + batch[n] * DD);
    float acc = 0.f;
#pragma unroll
    for (int i = 0; i < 2; i++) {
        const float4 a = o4[lane + i * 32];
        const float4 b = h4[lane + i * 32];
        acc = fmaf(a.x, b.x, acc);
        acc = fmaf(a.y, b.y, acc);
        acc = fmaf(a.z, b.z, acc);
        acc = fmaf(a.w, b.w, acc);
    }
#pragma unroll
    for (int o = 16; o > 0; o >>= 1) acc += __shfl_xor_sync(0xFFFFFFFFu, acc, o);
    if (lane == 0) g_e[n] = acc;
}

// segment softmax + weighted sum + write q_star = [h | r]; one block per graph
__global__ void k_pool() {
    __shared__ float red_[256];
    __shared__ float m_s, s_s;
    const int b = blockIdx.x, tid = threadIdx.x;
    const int s0 = g_start[b], s1 = g_start[b + 1];
    float r_acc = 0.f;
    if (s1 > s0) {
        float lm = -INFINITY;
        for (int n = s0 + tid; n < s1; n += 256) lm = fmaxf(lm, g_e[n]);
        red_[tid] = lm;
        __syncthreads();
        for (int o = 128; o > 0; o >>= 1) {
            if (tid < o) red_[tid] = fmaxf(red_[tid], red_[tid + o]);
            __syncthreads();
        }
        if (tid == 0) m_s = red_[0];
        __syncthreads();
        const float m = m_s;
        float ls = 0.f;
        for (int n = s0 + tid; n < s1; n += 256) ls += expf(g_e[n] - m);
        red_[tid] = ls;
        __syncthreads();
        for (int o = 128; o > 0; o >>= 1) {
            if (tid < o) red_[tid] += red_[tid + o];
            __syncthreads();
        }
        if (tid == 0) s_s = red_[0];
        __syncthreads();
        const float inv = 1.f / s_s;
        for (int n = s0; n < s1; n++) {
            const float w = expf(g_e[n] - m) * inv;
            r_acc = fmaf(w, g_out[(size_t)n * DD + tid], r_acc);
        }
    }
    g_qstar[b * 2 * DD + tid] = g_h[b * DD + tid];
    g_qstar[b * 2 * DD + DD + tid] = r_acc;
}

// y = relu(qstar @ W1 + b1) @ W2 + b2; one block per graph
__global__ void k_readout(const float* __restrict__ W1, const float* __restrict__ b1,
                          const float* __restrict__ W2, const float* __restrict__ b2,
                          float* __restrict__ y) {
    __shared__ float qv[2 * DD];
    __shared__ float red_[256];
    const int b = blockIdx.x, tid = threadIdx.x;
    qv[tid] = g_qstar[b * 2 * DD + tid];
    qv[DD + tid] = g_qstar[b * 2 * DD + DD + tid];
    __syncthreads();
    float acc = b1[tid];
    for (int k = 0; k < 2 * DD; k++) acc = fmaf(qv[k], W1[k * DD + tid], acc);
    red_[tid] = fmaxf(acc, 0.f) * W2[tid];
    __syncthreads();
    for (int o = 128; o > 0; o >>= 1) {
        if (tid < o) red_[tid] += red_[tid + o];
        __syncthreads();
    }
    if (tid == 0) y[b] = red_[0] + b2[0];
}

// ---------------- launch ----------------
extern "C" void kernel_launch(void* const* d_in, const int* in_sizes, int n_in,
                              void* d_out, int out_size) {
    const float* x     = (const float*)d_in[0];
    const float* eattr = (const float*)d_in[1];
    const float* W0    = (const float*)d_in[2];
    const float* b0v   = (const float*)d_in[3];
    const float* Wm1   = (const float*)d_in[4];
    const float* bm1   = (const float*)d_in[5];
    const float* Wm2   = (const float*)d_in[6];
    const float* bm2   = (const float*)d_in[7];
    const float* Wr    = (const float*)d_in[8];
    const float* br    = (const float*)d_in[9];
    const float* Wih   = (const float*)d_in[10];
    const float* Whh   = (const float*)d_in[11];
    const float* bl    = (const float*)d_in[12];
    const float* W1    = (const float*)d_in[13];
    const float* b1    = (const float*)d_in[14];
    const float* W2    = (const float*)d_in[15];
    const float* b2    = (const float*)d_in[16];
    const int*   ei    = (const int*)d_in[17];
    const int*   batch = (const int*)d_in[18];

    k_zero<<<256, 256>>>();
    k_offsets<<<(N_NODES + 255) / 256, 256>>>(batch);
    k_prepw<<<3072, 256>>>(Wm1, Wm2, Wr, Wih, Whh);
    k_prepea<<<(N_EDGES * 2 + 255) / 256, 256>>>(eattr);
    k_lin0<<<(N_NODES + 15) / 16, 256>>>(x, W0, b0v);
    k_ngemm<0><<<dim3(NPAD / 128, 2), 256, 40960>>>(br, bm2);   // P
    k_edge2<<<N_EDGES / 128, 256>>>(ei, bm1);                   // S, deg
    k_ngemm<1><<<dim3(NPAD / 128, 2), 256, 40960>>>(br, bm2);   // out (S converted inline)
    for (int s = 0; s < 3; s++) {
        k_gates<<<NG / 4, 256>>>(bl);
        k_attn<<<(N_NODES * 32 + 255) / 256, 256>>>(batch);
        k_pool<<<NG, 256>>>();
    }
    k_readout<<<NG, 256>>>(W1, b1, W2, b2, (float*)d_out);
}